// round 3
// baseline (speedup 1.0000x reference)
#include <cuda_runtime.h>
#include <cstdint>

#define EMBD  1024
#define NH    16
#define DH    64
#define BATCH 2
#define SEQ   2048
#define MROWS (BATCH*SEQ)     // 4096

// ---------------- scratch (device globals: allocation-free) ----------------
__device__ float g_q[BATCH*NH*SEQ*DH];     // [b,h,s,d]  16 MB
__device__ float g_k[BATCH*NH*SEQ*DH];     // 16 MB
__device__ float g_v[BATCH*NH*SEQ*DH];     // 16 MB
__device__ float g_attn[MROWS*EMBD];       // [b,s,h*d]  16 MB

// ============================================================================
// NT GEMM mainloop: C[128x128] tile of A[M,K(=1024)] * B[N,K]^T
// A, B row-major with K contiguous (lda = ldb = EMBD).
// 256 threads, 8x8 microtile per thread. As/Bs stored [k][m] transposed,
// stride 132 floats (pad, multiple of 4) for conflict-free float4 loads.
// ============================================================================
#define BK 16
#define TSTRIDE 132

__device__ __forceinline__ void gemm_mainloop(
    const float* __restrict__ A, const float* __restrict__ B,
    int m0, int n0, int tid, float (&acc)[8][8],
    float* As, float* Bs)
{
    const int tx = tid & 15;
    const int ty = tid >> 4;

    #pragma unroll
    for (int i = 0; i < 8; i++)
        #pragma unroll
        for (int j = 0; j < 8; j++)
            acc[i][j] = 0.f;

    for (int kt = 0; kt < EMBD / BK; ++kt) {
        // ---- load A tile (128x16) transposed into As[k][m] ----
        #pragma unroll
        for (int r = 0; r < 2; ++r) {
            int id = tid + r * 256;        // 0..511
            int mm = id >> 2;              // 0..127
            int kq = id & 3;               // 0..3 (float4 index)
            float4 v = *(const float4*)(A + (size_t)(m0 + mm) * EMBD + kt * BK + kq * 4);
            As[(kq*4+0)*TSTRIDE + mm] = v.x;
            As[(kq*4+1)*TSTRIDE + mm] = v.y;
            As[(kq*4+2)*TSTRIDE + mm] = v.z;
            As[(kq*4+3)*TSTRIDE + mm] = v.w;
        }
        // ---- load B tile (128x16) transposed into Bs[k][n] ----
        #pragma unroll
        for (int r = 0; r < 2; ++r) {
            int id = tid + r * 256;
            int nn = id >> 2;
            int kq = id & 3;
            float4 v = *(const float4*)(B + (size_t)(n0 + nn) * EMBD + kt * BK + kq * 4);
            Bs[(kq*4+0)*TSTRIDE + nn] = v.x;
            Bs[(kq*4+1)*TSTRIDE + nn] = v.y;
            Bs[(kq*4+2)*TSTRIDE + nn] = v.z;
            Bs[(kq*4+3)*TSTRIDE + nn] = v.w;
        }
        __syncthreads();

        #pragma unroll
        for (int kk = 0; kk < BK; ++kk) {
            float4 a0 = *(const float4*)(As + kk*TSTRIDE + ty*8);
            float4 a1 = *(const float4*)(As + kk*TSTRIDE + ty*8 + 4);
            float4 b0 = *(const float4*)(Bs + kk*TSTRIDE + tx*8);
            float4 b1 = *(const float4*)(Bs + kk*TSTRIDE + tx*8 + 4);
            float a[8] = {a0.x,a0.y,a0.z,a0.w,a1.x,a1.y,a1.z,a1.w};
            float b[8] = {b0.x,b0.y,b0.z,b0.w,b1.x,b1.y,b1.z,b1.w};
            #pragma unroll
            for (int i = 0; i < 8; i++)
                #pragma unroll
                for (int j = 0; j < 8; j++)
                    acc[i][j] += a[i] * b[j];
        }
        __syncthreads();
    }
}

// QKV GEMM: C = x @ W_in^T + b_in, scattered into g_q/g_k/g_v [b,h,s,d]
__global__ __launch_bounds__(256)
void gemm_qkv_kernel(const float* __restrict__ A, const float* __restrict__ B,
                     const float* __restrict__ bias)
{
    __shared__ float As[BK * TSTRIDE];
    __shared__ float Bs[BK * TSTRIDE];
    const int tid = threadIdx.x;
    const int tx = tid & 15, ty = tid >> 4;
    const int m0 = blockIdx.y * 128;
    const int n0 = blockIdx.x * 128;

    float acc[8][8];
    gemm_mainloop(A, B, m0, n0, tid, acc, As, Bs);

    // n0..n0+127 sits inside one of the three 1024-wide q/k/v bands
    const int sel = n0 >> 10;
    float* dstbuf = (sel == 0) ? g_q : (sel == 1) ? g_k : g_v;

    #pragma unroll
    for (int i = 0; i < 8; i++) {
        int m = m0 + ty * 8 + i;
        int bb = m >> 11;          // batch
        int ss = m & 2047;         // seq
        #pragma unroll
        for (int j = 0; j < 8; j++) {
            int n  = n0 + tx * 8 + j;
            int hn = (n & 1023) >> 6;
            int dd = n & 63;
            float cv = acc[i][j] + bias[n];
            dstbuf[(((size_t)(bb * NH + hn)) * SEQ + ss) * DH + dd] = cv;
        }
    }
}

// Output projection: out = g_attn @ W_out^T + b_out  (plain [M,N] store)
__global__ __launch_bounds__(256)
void gemm_out_kernel(const float* __restrict__ B, const float* __restrict__ bias,
                     float* __restrict__ C)
{
    __shared__ float As[BK * TSTRIDE];
    __shared__ float Bs[BK * TSTRIDE];
    const int tid = threadIdx.x;
    const int tx = tid & 15, ty = tid >> 4;
    const int m0 = blockIdx.y * 128;
    const int n0 = blockIdx.x * 128;

    float acc[8][8];
    gemm_mainloop(g_attn, B, m0, n0, tid, acc, As, Bs);

    #pragma unroll
    for (int i = 0; i < 8; i++) {
        int m = m0 + ty * 8 + i;
        #pragma unroll
        for (int j = 0; j < 8; j++) {
            int n = n0 + tx * 8 + j;
            C[(size_t)m * EMBD + n] = acc[i][j] + bias[n];
        }
    }
}

// ============================================================================
// Flash attention, fp32. One block = 64 q-rows of one (b,h).
// 256 threads as 16x16; each thread owns a 4x4 S/P tile and 4x4 O tile.
// smem: Qt[d][qr], KV (K as [d][kc], then V as [kc][d]), Pst[kc][qr].
// Pad stride SD=68: multiple of 4 so float4 smem loads stay 16B-aligned.
// ============================================================================
#define SD 68

__global__ __launch_bounds__(256)
void attn_kernel()
{
    extern __shared__ float sm[];
    float* Qt  = sm;                  // 64*SD
    float* KV  = sm + 64 * SD;        // 64*SD
    float* Pst = sm + 2 * 64 * SD;    // 64*SD

    const int tid = threadIdx.x;
    const int tx = tid & 15, ty = tid >> 4;
    const int bh = blockIdx.y;                 // 0..31
    const int q0 = blockIdx.x * 64;

    const float* Qb = g_q + (size_t)bh * SEQ * DH;
    const float* Kb = g_k + (size_t)bh * SEQ * DH;
    const float* Vb = g_v + (size_t)bh * SEQ * DH;

    // load Q tile transposed: Qt[d][qr]
    #pragma unroll
    for (int r = 0; r < 4; ++r) {
        int idx = tid + r * 256;       // 0..1023
        int row = idx >> 4;            // 0..63
        int dq  = idx & 15;
        float4 v = *(const float4*)(Qb + (size_t)(q0 + row) * DH + dq * 4);
        Qt[(dq*4+0)*SD + row] = v.x;
        Qt[(dq*4+1)*SD + row] = v.y;
        Qt[(dq*4+2)*SD + row] = v.z;
        Qt[(dq*4+3)*SD + row] = v.w;
    }

    float m_[4], l_[4], acc[4][4];
    #pragma unroll
    for (int i = 0; i < 4; i++) {
        m_[i] = __int_as_float(0xff800000);   // -inf
        l_[i] = 0.f;
        #pragma unroll
        for (int j = 0; j < 4; j++) acc[i][j] = 0.f;
    }

    for (int kt = 0; kt < SEQ / 64; ++kt) {
        __syncthreads();   // prior V reads done before overwriting KV
        // load K tile transposed: KV[d][kc]
        #pragma unroll
        for (int r = 0; r < 4; ++r) {
            int idx = tid + r * 256;
            int row = idx >> 4;
            int dq  = idx & 15;
            float4 v = *(const float4*)(Kb + (size_t)(kt*64 + row) * DH + dq * 4);
            KV[(dq*4+0)*SD + row] = v.x;
            KV[(dq*4+1)*SD + row] = v.y;
            KV[(dq*4+2)*SD + row] = v.z;
            KV[(dq*4+3)*SD + row] = v.w;
        }
        __syncthreads();

        // S = Q K^T (4x4 per thread)
        float s[4][4];
        #pragma unroll
        for (int i = 0; i < 4; i++)
            #pragma unroll
            for (int j = 0; j < 4; j++) s[i][j] = 0.f;

        #pragma unroll 16
        for (int d = 0; d < 64; ++d) {
            float4 a = *(const float4*)(Qt + d*SD + ty*4);
            float4 b = *(const float4*)(KV + d*SD + tx*4);
            float av[4] = {a.x,a.y,a.z,a.w};
            float bv[4] = {b.x,b.y,b.z,b.w};
            #pragma unroll
            for (int i = 0; i < 4; i++)
                #pragma unroll
                for (int j = 0; j < 4; j++)
                    s[i][j] += av[i] * bv[j];
        }

        // online softmax (row groups = 16 consecutive lanes sharing ty)
        #pragma unroll
        for (int i = 0; i < 4; i++) {
            #pragma unroll
            for (int j = 0; j < 4; j++) s[i][j] *= 0.125f;   // 1/sqrt(64)
            float mx = fmaxf(fmaxf(s[i][0], s[i][1]), fmaxf(s[i][2], s[i][3]));
            #pragma unroll
            for (int off = 8; off > 0; off >>= 1)
                mx = fmaxf(mx, __shfl_xor_sync(0xffffffffu, mx, off));
            float mn = fmaxf(m_[i], mx);
            float alpha = __expf(m_[i] - mn);
            m_[i] = mn;
            float rs = 0.f;
            #pragma unroll
            for (int j = 0; j < 4; j++) {
                float p = __expf(s[i][j] - mn);
                s[i][j] = p;
                rs += p;
            }
            #pragma unroll
            for (int off = 8; off > 0; off >>= 1)
                rs += __shfl_xor_sync(0xffffffffu, rs, off);
            l_[i] = l_[i] * alpha + rs;
            #pragma unroll
            for (int j = 0; j < 4; j++) acc[i][j] *= alpha;
        }

        // stage P transposed: Pst[kc][qr]
        #pragma unroll
        for (int j = 0; j < 4; j++)
            #pragma unroll
            for (int i = 0; i < 4; i++)
                Pst[(tx*4 + j)*SD + (ty*4 + i)] = s[i][j];
        __syncthreads();   // Pst ready; K reads done

        // load V tile: KV[kc][d]
        #pragma unroll
        for (int r = 0; r < 4; ++r) {
            int idx = tid + r * 256;
            int row = idx >> 4;
            int dq  = idx & 15;
            float4 v = *(const float4*)(Vb + (size_t)(kt*64 + row) * DH + dq * 4);
            *(float4*)(KV + row*SD + dq*4) = v;
        }
        __syncthreads();

        // O += P @ V
        #pragma unroll 16
        for (int kc = 0; kc < 64; ++kc) {
            float4 a = *(const float4*)(Pst + kc*SD + ty*4);
            float4 b = *(const float4*)(KV  + kc*SD + tx*4);
            float av[4] = {a.x,a.y,a.z,a.w};
            float bv[4] = {b.x,b.y,b.z,b.w};
            #pragma unroll
            for (int i = 0; i < 4; i++)
                #pragma unroll
                for (int j = 0; j < 4; j++)
                    acc[i][j] += av[i] * bv[j];
        }
    }

    // epilogue: O /= l, write to [b,s,h*d]
    const int bb = bh >> 4;
    const int hh = bh & 15;
    #pragma unroll
    for (int i = 0; i < 4; i++) {
        float inv = 1.0f / l_[i];
        int srow = q0 + ty * 4 + i;
        float* dst = g_attn + ((size_t)(bb * SEQ + srow)) * EMBD + hh * DH + tx * 4;
        float4 o;
        o.x = acc[i][0] * inv;
        o.y = acc[i][1] * inv;
        o.z = acc[i][2] * inv;
        o.w = acc[i][3] * inv;
        *(float4*)dst = o;
    }
}

// ============================================================================
extern "C" void kernel_launch(void* const* d_in, const int* in_sizes, int n_in,
                              void* d_out, int out_size)
{
    const float* x     = (const float*)d_in[0];
    const float* W_in  = (const float*)d_in[1];
    const float* b_in  = (const float*)d_in[2];
    const float* W_out = (const float*)d_in[3];
    const float* b_out = (const float*)d_in[4];
    float* out = (float*)d_out;

    cudaFuncSetAttribute(attn_kernel,
                         cudaFuncAttributeMaxDynamicSharedMemorySize,
                         3 * 64 * SD * sizeof(float));

    dim3 thr(256);
    // QKV: M=4096, N=3072, K=1024
    gemm_qkv_kernel<<<dim3(3072/128, MROWS/128), thr>>>(x, W_in, b_in);
    // attention: 32 q-tiles x 32 (b,h)
    attn_kernel<<<dim3(SEQ/64, BATCH*NH), thr, 3*64*SD*sizeof(float)>>>();
    // out proj: M=4096, N=1024, K=1024
    gemm_out_kernel<<<dim3(EMBD/128, MROWS/128), thr>>>(W_out, b_out, out);
}

// round 6
// speedup vs baseline: 1.6538x; 1.6538x over previous
#include <cuda_runtime.h>
#include <cuda_fp16.h>
#include <cstdint>

#define EMBD  1024
#define NH    16
#define DH    64
#define BATCH 2
#define SEQ   2048
#define MROWS 4096
#define KDIM  1024

// ---------------- scratch (device globals: allocation-free) ----------------
__device__ __align__(16) __half g_xh[MROWS*KDIM];
__device__ __align__(16) __half g_xl[MROWS*KDIM];
__device__ __align__(16) __half g_wih[3*EMBD*KDIM];
__device__ __align__(16) __half g_wil[3*EMBD*KDIM];
__device__ __align__(16) __half g_woh[EMBD*KDIM];
__device__ __align__(16) __half g_wol[EMBD*KDIM];
__device__ __align__(16) __half g_qh[BATCH*NH*SEQ*DH];
__device__ __align__(16) __half g_ql[BATCH*NH*SEQ*DH];
__device__ __align__(16) __half g_kh[BATCH*NH*SEQ*DH];
__device__ __align__(16) __half g_kl[BATCH*NH*SEQ*DH];
__device__ __align__(16) __half g_vh[BATCH*NH*SEQ*DH];
__device__ __align__(16) __half g_vl[BATCH*NH*SEQ*DH];
__device__ __align__(16) __half g_ah[MROWS*EMBD];
__device__ __align__(16) __half g_al[MROWS*EMBD];

// ---------------- PTX helpers (all sm_80-level: valid on compute_103) ------
__device__ __forceinline__ uint32_t smem_u32(const void* p) {
    uint32_t a;
    asm("{ .reg .u64 t; cvta.to.shared.u64 t, %1; cvt.u32.u64 %0, t; }" : "=r"(a) : "l"(p));
    return a;
}
#define CPA16(dst, src) asm volatile("cp.async.cg.shared.global [%0], [%1], 16;" :: "r"(dst), "l"(src))
#define CPC()   asm volatile("cp.async.commit_group;" ::: "memory")
#define CPW(n)  asm volatile("cp.async.wait_group %0;" :: "n"(n) : "memory")

#define LDSM4(r0,r1,r2,r3,a) \
    asm volatile("ldmatrix.sync.aligned.m8n8.x4.shared.b16 {%0,%1,%2,%3}, [%4];" \
        : "=r"(r0),"=r"(r1),"=r"(r2),"=r"(r3) : "r"(a))
#define LDSM2(r0,r1,a) \
    asm volatile("ldmatrix.sync.aligned.m8n8.x2.shared.b16 {%0,%1}, [%2];" \
        : "=r"(r0),"=r"(r1) : "r"(a))
#define LDSM2T(r0,r1,a) \
    asm volatile("ldmatrix.sync.aligned.m8n8.x2.trans.shared.b16 {%0,%1}, [%2];" \
        : "=r"(r0),"=r"(r1) : "r"(a))

#define MMA(d, a, b) \
    asm volatile("mma.sync.aligned.m16n8k16.row.col.f32.f16.f16.f32 " \
        "{%0,%1,%2,%3},{%4,%5,%6,%7},{%8,%9},{%0,%1,%2,%3};" \
        : "+f"((d)[0]),"+f"((d)[1]),"+f"((d)[2]),"+f"((d)[3]) \
        : "r"((a)[0]),"r"((a)[1]),"r"((a)[2]),"r"((a)[3]),"r"((b)[0]),"r"((b)[1]))

__device__ __forceinline__ uint32_t packh2(float a, float b) {
    __half2 h = __halves2half2(__float2half_rn(a), __float2half_rn(b));
    return *reinterpret_cast<uint32_t*>(&h);
}

// ---------------- fp32 -> fp16 hi/lo split ----------------
__global__ __launch_bounds__(256)
void cvt_kernel(const float* __restrict__ s, __half* __restrict__ hi,
                __half* __restrict__ lo, int n4)
{
    int i = blockIdx.x * 256 + threadIdx.x;
    if (i >= n4) return;
    float4 v = ((const float4*)s)[i];
    __half h0 = __float2half_rn(v.x), h1 = __float2half_rn(v.y);
    __half h2 = __float2half_rn(v.z), h3 = __float2half_rn(v.w);
    __half l0 = __float2half_rn(v.x - __half2float(h0));
    __half l1 = __float2half_rn(v.y - __half2float(h1));
    __half l2 = __float2half_rn(v.z - __half2float(h2));
    __half l3 = __float2half_rn(v.w - __half2float(h3));
    ((__half2*)hi)[2*i]   = __halves2half2(h0, h1);
    ((__half2*)hi)[2*i+1] = __halves2half2(h2, h3);
    ((__half2*)lo)[2*i]   = __halves2half2(l0, l1);
    ((__half2*)lo)[2*i+1] = __halves2half2(l2, l3);
}

// ============================================================================
// HMMA NT GEMM: C[128x128] = (Ah+Al)[M,K] * (Bh+Bl)[N,K]^T, K=1024.
// BK=32, 3-stage cp.async pipeline. 8 warps (2x4), warp tile 64x32.
// smem rows padded to 80B (40 halves): conflict-free ldmatrix + cp.async.
// mode 0: QKV epilogue (bias + split fp16 -> g_q/k/v hi,lo per-head layout)
// mode 1: out-proj epilogue (bias + fp32 store)
// ============================================================================
#define GSTG   40960            // bytes per stage: 4 tiles * 128 rows * 80B
#define GSMEM  (3*GSTG)

__global__ __launch_bounds__(256, 1)
void gemm_tc(const __half* __restrict__ Ah, const __half* __restrict__ Al,
             const __half* __restrict__ Bh, const __half* __restrict__ Bl,
             const float* __restrict__ bias, float* __restrict__ outp, int mode)
{
    extern __shared__ char smg[];
    const uint32_t smb = smem_u32(smg);
    const int tid = threadIdx.x, lane = tid & 31, wid = tid >> 5;
    const int wm = wid >> 2, wn = wid & 3;          // 2 x 4 warp grid
    const int m0 = blockIdx.y * 128, n0 = blockIdx.x * 128;

    const __half* srcs[4] = {Ah, Al, Bh, Bl};

    auto issue_stage = [&](int kt, int st) {
        #pragma unroll
        for (int it = 0; it < 8; ++it) {
            int idx = it * 256 + tid;           // 0..2047
            int tile = idx >> 9;                // 0..3
            int t2 = idx & 511;
            int row = t2 >> 2, seg = t2 & 3;    // 128 rows x 4 16B-segs
            int grow = (tile < 2 ? m0 : n0) + row;
            const __half* src = srcs[tile] + (size_t)grow * KDIM + kt * 32 + seg * 8;
            uint32_t dst = smb + st * GSTG + tile * 10240 + row * 80 + seg * 16;
            CPA16(dst, src);
        }
    };

    float acc[4][4][4];
    #pragma unroll
    for (int i = 0; i < 4; i++)
        #pragma unroll
        for (int j = 0; j < 4; j++)
            #pragma unroll
            for (int r = 0; r < 4; r++) acc[i][j][r] = 0.f;

    issue_stage(0, 0); CPC();
    issue_stage(1, 1); CPC();

    const int NK = KDIM / 32;
    for (int kt = 0; kt < NK; ++kt) {
        CPW(1);
        __syncthreads();
        if (kt + 2 < NK) { issue_stage(kt + 2, (kt + 2) % 3); CPC(); }

        const uint32_t base = smb + (kt % 3) * GSTG;
        #pragma unroll
        for (int ks = 0; ks < 2; ++ks) {
            uint32_t a_h[4][4], a_l[4][4];
            const int acol = ks * 16 + ((lane >> 4) << 3);
            #pragma unroll
            for (int i = 0; i < 4; ++i) {
                int r = wm * 64 + i * 16 + (lane & 15);
                uint32_t ad = base + r * 80 + acol * 2;
                LDSM4(a_h[i][0], a_h[i][1], a_h[i][2], a_h[i][3], ad);
                LDSM4(a_l[i][0], a_l[i][1], a_l[i][2], a_l[i][3], ad + 10240);
            }
            const int bcol = ks * 16 + (((lane >> 3) & 1) << 3);
            #pragma unroll
            for (int j = 0; j < 4; ++j) {
                int r = wn * 32 + j * 8 + (lane & 7);
                uint32_t bd = base + 20480 + r * 80 + bcol * 2;
                uint32_t b_h[2], b_l[2];
                LDSM2(b_h[0], b_h[1], bd);
                LDSM2(b_l[0], b_l[1], bd + 10240);
                #pragma unroll
                for (int i = 0; i < 4; ++i) {
                    MMA(acc[i][j], a_h[i], b_h);
                    MMA(acc[i][j], a_l[i], b_h);
                    MMA(acc[i][j], a_h[i], b_l);
                }
            }
        }
    }
    __syncthreads();

    // ---------------- epilogue ----------------
    const int g = lane >> 2, tg = lane & 3;
    if (mode == 0) {
        const int sel = (blockIdx.x * 128) >> 10;    // 0=q 1=k 2=v
        __half* dh = (sel == 0) ? g_qh : (sel == 1) ? g_kh : g_vh;
        __half* dl = (sel == 0) ? g_ql : (sel == 1) ? g_kl : g_vl;
        #pragma unroll
        for (int i = 0; i < 4; ++i) {
            #pragma unroll
            for (int j = 0; j < 4; ++j) {
                int n = n0 + wn * 32 + j * 8 + tg * 2;
                int hh = (n & 1023) >> 6, dd = n & 63;
                float b0 = __ldg(bias + n), b1 = __ldg(bias + n + 1);
                #pragma unroll
                for (int rr = 0; rr < 2; ++rr) {
                    int m = m0 + wm * 64 + i * 16 + g + rr * 8;
                    int bb = m >> 11, ss = m & 2047;
                    float v0 = acc[i][j][rr*2+0] + b0;
                    float v1 = acc[i][j][rr*2+1] + b1;
                    __half h0 = __float2half_rn(v0), h1 = __float2half_rn(v1);
                    size_t o = (((size_t)(bb * NH + hh)) * SEQ + ss) * DH + dd;
                    *(__half2*)&dh[o] = __halves2half2(h0, h1);
                    *(__half2*)&dl[o] = __halves2half2(
                        __float2half_rn(v0 - __half2float(h0)),
                        __float2half_rn(v1 - __half2float(h1)));
                }
            }
        }
    } else {
        #pragma unroll
        for (int i = 0; i < 4; ++i) {
            #pragma unroll
            for (int j = 0; j < 4; ++j) {
                int n = n0 + wn * 32 + j * 8 + tg * 2;
                float b0 = __ldg(bias + n), b1 = __ldg(bias + n + 1);
                #pragma unroll
                for (int rr = 0; rr < 2; ++rr) {
                    int m = m0 + wm * 64 + i * 16 + g + rr * 8;
                    float2 w;
                    w.x = acc[i][j][rr*2+0] + b0;
                    w.y = acc[i][j][rr*2+1] + b1;
                    *(float2*)&outp[(size_t)m * EMBD + n] = w;
                }
            }
        }
    }
}

// ============================================================================
// Flash attention, HMMA fp16-split. CTA = 128 q-rows of one (b,h); 8 warps,
// 16 q-rows each. K/V tiles (64 rows) double-buffered via cp.async.
// smem half-stride 72 (144B rows): conflict-free ldmatrix (incl. trans).
// ============================================================================
#define QTILE  9216            // 128*72 halves
#define KVTILE 4608            // 64*72 halves
#define KVBUF  (4*KVTILE)      // Kh,Kl,Vh,Vl
#define ASMEM  ((2*QTILE + 2*KVBUF) * 2)   // bytes = 110592

__global__ __launch_bounds__(256, 1)
void attn_mma()
{
    extern __shared__ __half smh[];
    const uint32_t smb = smem_u32(smh);
    const int tid = threadIdx.x, lane = tid & 31, w = tid >> 5;
    const int g = lane >> 2, tg = lane & 3;
    const int bh = blockIdx.y;
    const int q0 = blockIdx.x * 128;
    const size_t hb = (size_t)bh * SEQ * DH;

    const uint32_t Qh_o = 0, Ql_o = QTILE;
    const uint32_t KV_o = 2 * QTILE;

    // ---- prologue: Q (both tiles) + KV tile 0 -> buf0 ; then KV1 -> buf1
    #pragma unroll
    for (int it = 0; it < 8; ++it) {
        int idx = it * 256 + tid;              // 0..2047
        int tile = idx >> 10;                  // 0: Qh, 1: Ql
        int t2 = idx & 1023;
        int row = t2 >> 3, seg = t2 & 7;
        const __half* src = (tile ? g_ql : g_qh) + hb + (size_t)(q0 + row) * DH + seg * 8;
        CPA16(smb + (tile ? Ql_o : Qh_o) * 2 + (row * 72 + seg * 8) * 2, src);
    }
    const __half* kvsrc[4] = {g_kh, g_kl, g_vh, g_vl};
    auto issue_kv = [&](int kt, int b) {
        #pragma unroll
        for (int it = 0; it < 8; ++it) {
            int idx = it * 256 + tid;          // 0..2047
            int tile = idx >> 9;               // Kh,Kl,Vh,Vl
            int t2 = idx & 511;
            int row = t2 >> 3, seg = t2 & 7;
            const __half* src = kvsrc[tile] + hb + (size_t)(kt * 64 + row) * DH + seg * 8;
            uint32_t dst = smb + (KV_o + b * KVBUF + tile * KVTILE + row * 72 + seg * 8) * 2;
            CPA16(dst, src);
        }
    };
    issue_kv(0, 0); CPC();
    issue_kv(1, 1); CPC();

    float o[8][4], m_[2], l_[2];
    #pragma unroll
    for (int j = 0; j < 8; j++)
        #pragma unroll
        for (int r = 0; r < 4; r++) o[j][r] = 0.f;
    m_[0] = m_[1] = __int_as_float(0xff800000);
    l_[0] = l_[1] = 0.f;

    const int NT = SEQ / 64;
    for (int kt = 0; kt < NT; ++kt) {
        const int b = kt & 1;
        const uint32_t kvb = KV_o + b * KVBUF;
        CPW(1);
        __syncthreads();

        // ---- S = Q K^T (fp32, 3-way split) ----
        float s[8][4];
        #pragma unroll
        for (int j = 0; j < 8; j++)
            #pragma unroll
            for (int r = 0; r < 4; r++) s[j][r] = 0.f;

        #pragma unroll
        for (int ds = 0; ds < 4; ++ds) {
            uint32_t qh4[4], ql4[4];
            {
                int r = w * 16 + (lane & 15);
                int col = ds * 16 + ((lane >> 4) << 3);
                uint32_t ad = smb + (r * 72 + col) * 2;
                LDSM4(qh4[0], qh4[1], qh4[2], qh4[3], ad + Qh_o * 2);
                LDSM4(ql4[0], ql4[1], ql4[2], ql4[3], ad + Ql_o * 2);
            }
            int bcol = ds * 16 + (((lane >> 3) & 1) << 3);
            #pragma unroll
            for (int j = 0; j < 8; ++j) {
                int r = j * 8 + (lane & 7);
                uint32_t kd = smb + (kvb + r * 72 + bcol) * 2;
                uint32_t kh2[2], kl2[2];
                LDSM2(kh2[0], kh2[1], kd);
                LDSM2(kl2[0], kl2[1], kd + KVTILE * 2);
                MMA(s[j], qh4, kh2);
                MMA(s[j], ql4, kh2);
                MMA(s[j], qh4, kl2);
            }
        }

        // ---- online softmax (rows g, g+8) ----
        #pragma unroll
        for (int rr = 0; rr < 2; ++rr) {
            float mx = m_[rr];
            #pragma unroll
            for (int j = 0; j < 8; ++j) {
                float v0 = s[j][rr*2+0] * 0.125f, v1 = s[j][rr*2+1] * 0.125f;
                s[j][rr*2+0] = v0; s[j][rr*2+1] = v1;
                mx = fmaxf(mx, fmaxf(v0, v1));
            }
            mx = fmaxf(mx, __shfl_xor_sync(0xffffffffu, mx, 1));
            mx = fmaxf(mx, __shfl_xor_sync(0xffffffffu, mx, 2));
            float alpha = __expf(m_[rr] - mx);
            m_[rr] = mx;
            float rs = 0.f;
            #pragma unroll
            for (int j = 0; j < 8; ++j) {
                float e0 = __expf(s[j][rr*2+0] - mx);
                float e1 = __expf(s[j][rr*2+1] - mx);
                s[j][rr*2+0] = e0; s[j][rr*2+1] = e1;
                rs += e0 + e1;
            }
            rs += __shfl_xor_sync(0xffffffffu, rs, 1);
            rs += __shfl_xor_sync(0xffffffffu, rs, 2);
            l_[rr] = l_[rr] * alpha + rs;
            #pragma unroll
            for (int j = 0; j < 8; ++j) {
                o[j][rr*2+0] *= alpha;
                o[j][rr*2+1] *= alpha;
            }
        }

        // ---- O += P V (P split in registers, V split from smem) ----
        #pragma unroll
        for (int ks = 0; ks < 4; ++ks) {
            uint32_t pa_h[4], pa_l[4];
            #pragma unroll
            for (int half2i = 0; half2i < 2; ++half2i) {
                float* f = s[ks * 2 + half2i];
                float h00, h01, h10, h11;
                __half t0 = __float2half_rn(f[0]); h00 = __half2float(t0);
                __half t1 = __float2half_rn(f[1]); h01 = __half2float(t1);
                __half t2 = __float2half_rn(f[2]); h10 = __half2float(t2);
                __half t3 = __float2half_rn(f[3]); h11 = __half2float(t3);
                pa_h[half2i*2+0] = packh2(f[0], f[1]);
                pa_h[half2i*2+1] = packh2(f[2], f[3]);
                pa_l[half2i*2+0] = packh2(f[0] - h00, f[1] - h01);
                pa_l[half2i*2+1] = packh2(f[2] - h10, f[3] - h11);
            }
            // reorder: {a0,a1,a2,a3} = {f0r0, f0r1, f1r0, f1r1} already in order
            int vrow = ks * 16 + (lane & 15);
            #pragma unroll
            for (int jn = 0; jn < 8; ++jn) {
                uint32_t vd = smb + (kvb + 2 * KVTILE + vrow * 72 + jn * 8) * 2;
                uint32_t vh2[2], vl2[2];
                LDSM2T(vh2[0], vh2[1], vd);
                LDSM2T(vl2[0], vl2[1], vd + KVTILE * 2);
                MMA(o[jn], pa_h, vh2);
                MMA(o[jn], pa_l, vh2);
                MMA(o[jn], pa_h, vl2);
            }
        }

        __syncthreads();
        if (kt + 2 < NT) { issue_kv(kt + 2, b); CPC(); }
    }

    // ---- epilogue: normalize, split fp16, store to g_ah/g_al ----
    const int bb = bh >> 4, hh = bh & 15;
    #pragma unroll
    for (int rr = 0; rr < 2; ++rr) {
        float inv = 1.0f / l_[rr];
        int sq = q0 + w * 16 + g + rr * 8;
        size_t rowo = ((size_t)(bb * SEQ + sq)) * EMBD + hh * DH;
        #pragma unroll
        for (int jn = 0; jn < 8; ++jn) {
            int dd = jn * 8 + tg * 2;
            float v0 = o[jn][rr*2+0] * inv;
            float v1 = o[jn][rr*2+1] * inv;
            __half h0 = __float2half_rn(v0), h1 = __float2half_rn(v1);
            *(__half2*)&g_ah[rowo + dd] = __halves2half2(h0, h1);
            *(__half2*)&g_al[rowo + dd] = __halves2half2(
                __float2half_rn(v0 - __half2float(h0)),
                __float2half_rn(v1 - __half2float(h1)));
        }
    }
}

// ============================================================================
extern "C" void kernel_launch(void* const* d_in, const int* in_sizes, int n_in,
                              void* d_out, int out_size)
{
    const float* x     = (const float*)d_in[0];
    const float* W_in  = (const float*)d_in[1];
    const float* b_in  = (const float*)d_in[2];
    const float* W_out = (const float*)d_in[3];
    const float* b_out = (const float*)d_in[4];
    float* out = (float*)d_out;

    cudaFuncSetAttribute(gemm_tc, cudaFuncAttributeMaxDynamicSharedMemorySize, GSMEM);
    cudaFuncSetAttribute(attn_mma, cudaFuncAttributeMaxDynamicSharedMemorySize, ASMEM);

    __half *xh, *xl, *wih, *wil, *woh, *wol, *ah, *al;
    cudaGetSymbolAddress((void**)&xh,  g_xh);
    cudaGetSymbolAddress((void**)&xl,  g_xl);
    cudaGetSymbolAddress((void**)&wih, g_wih);
    cudaGetSymbolAddress((void**)&wil, g_wil);
    cudaGetSymbolAddress((void**)&woh, g_woh);
    cudaGetSymbolAddress((void**)&wol, g_wol);
    cudaGetSymbolAddress((void**)&ah,  g_ah);
    cudaGetSymbolAddress((void**)&al,  g_al);

    // fp32 -> fp16 hi/lo splits
    cvt_kernel<<<(MROWS*KDIM/4)/256, 256>>>(x, xh, xl, MROWS*KDIM/4);
    cvt_kernel<<<(3*EMBD*KDIM/4)/256, 256>>>(W_in, wih, wil, 3*EMBD*KDIM/4);
    cvt_kernel<<<(EMBD*KDIM/4)/256, 256>>>(W_out, woh, wol, EMBD*KDIM/4);

    // QKV: [4096,3072] = X @ W_in^T + b_in -> split-scatter q/k/v (hi,lo)
    gemm_tc<<<dim3(3072/128, MROWS/128), 256, GSMEM>>>(xh, xl, wih, wil, b_in, nullptr, 0);

    // flash attention (HMMA, split)
    attn_mma<<<dim3(SEQ/128, BATCH*NH), 256, ASMEM>>>();

    // out-proj: [4096,1024] = Attn @ W_out^T + b_out
    gemm_tc<<<dim3(EMBD/128, MROWS/128), 256, GSMEM>>>(ah, al, woh, wol, b_out, out, 1);
}

// round 7
// speedup vs baseline: 2.6880x; 1.6253x over previous
#include <cuda_runtime.h>
#include <cuda_fp16.h>
#include <cstdint>

#define EMBD  1024
#define NH    16
#define DH    64
#define BATCH 2
#define SEQ   2048
#define MROWS 4096
#define KDIM  1024

// ---------------- scratch (device globals: allocation-free) ----------------
__device__ __align__(16) __half g_xh[MROWS*KDIM];
__device__ __align__(16) __half g_xl[MROWS*KDIM];
__device__ __align__(16) __half g_wih[3*EMBD*KDIM];
__device__ __align__(16) __half g_wil[3*EMBD*KDIM];
__device__ __align__(16) __half g_woh[EMBD*KDIM];
__device__ __align__(16) __half g_wol[EMBD*KDIM];
__device__ __align__(16) __half g_qh[BATCH*NH*SEQ*DH];
__device__ __align__(16) __half g_ql[BATCH*NH*SEQ*DH];
__device__ __align__(16) __half g_kh[BATCH*NH*SEQ*DH];
__device__ __align__(16) __half g_kl[BATCH*NH*SEQ*DH];
__device__ __align__(16) __half g_vh[BATCH*NH*SEQ*DH];
__device__ __align__(16) __half g_vl[BATCH*NH*SEQ*DH];
__device__ __align__(16) __half g_ah[MROWS*EMBD];
__device__ __align__(16) __half g_al[MROWS*EMBD];

// ---------------- PTX helpers (sm_80-level: valid under compute_103) -------
__device__ __forceinline__ uint32_t smem_u32(const void* p) {
    uint32_t a;
    asm("{ .reg .u64 t; cvta.to.shared.u64 t, %1; cvt.u32.u64 %0, t; }" : "=r"(a) : "l"(p));
    return a;
}
#define CPA16(dst, src) asm volatile("cp.async.cg.shared.global [%0], [%1], 16;" :: "r"(dst), "l"(src))
#define CPC()   asm volatile("cp.async.commit_group;" ::: "memory")
#define CPW(n)  asm volatile("cp.async.wait_group %0;" :: "n"(n) : "memory")

#define LDSM4(r0,r1,r2,r3,a) \
    asm volatile("ldmatrix.sync.aligned.m8n8.x4.shared.b16 {%0,%1,%2,%3}, [%4];" \
        : "=r"(r0),"=r"(r1),"=r"(r2),"=r"(r3) : "r"(a))
#define LDSM2(r0,r1,a) \
    asm volatile("ldmatrix.sync.aligned.m8n8.x2.shared.b16 {%0,%1}, [%2];" \
        : "=r"(r0),"=r"(r1) : "r"(a))
#define LDSM2T(r0,r1,a) \
    asm volatile("ldmatrix.sync.aligned.m8n8.x2.trans.shared.b16 {%0,%1}, [%2];" \
        : "=r"(r0),"=r"(r1) : "r"(a))

#define MMA(d, a, b) \
    asm volatile("mma.sync.aligned.m16n8k16.row.col.f32.f16.f16.f32 " \
        "{%0,%1,%2,%3},{%4,%5,%6,%7},{%8,%9},{%0,%1,%2,%3};" \
        : "+f"((d)[0]),"+f"((d)[1]),"+f"((d)[2]),"+f"((d)[3]) \
        : "r"((a)[0]),"r"((a)[1]),"r"((a)[2]),"r"((a)[3]),"r"((b)[0]),"r"((b)[1]))

__device__ __forceinline__ uint32_t packh2(float a, float b) {
    __half2 h = __halves2half2(__float2half_rn(a), __float2half_rn(b));
    return *reinterpret_cast<uint32_t*>(&h);
}

// ---------------- fp32 -> fp16 hi/lo split ----------------
__global__ __launch_bounds__(256)
void cvt_kernel(const float* __restrict__ s, __half* __restrict__ hi,
                __half* __restrict__ lo, int n4)
{
    int i = blockIdx.x * 256 + threadIdx.x;
    if (i >= n4) return;
    float4 v = ((const float4*)s)[i];
    __half h0 = __float2half_rn(v.x), h1 = __float2half_rn(v.y);
    __half h2 = __float2half_rn(v.z), h3 = __float2half_rn(v.w);
    __half l0 = __float2half_rn(v.x - __half2float(h0));
    __half l1 = __float2half_rn(v.y - __half2float(h1));
    __half l2 = __float2half_rn(v.z - __half2float(h2));
    __half l3 = __float2half_rn(v.w - __half2float(h3));
    ((__half2*)hi)[2*i]   = __halves2half2(h0, h1);
    ((__half2*)hi)[2*i+1] = __halves2half2(h2, h3);
    ((__half2*)lo)[2*i]   = __halves2half2(l0, l1);
    ((__half2*)lo)[2*i+1] = __halves2half2(l2, l3);
}

// ============================================================================
// HMMA NT GEMM: C[128x128] = (Ah+Al)[M,K] * (Bh+Bl)[N,K]^T, K=1024.
// BK=32, 3-stage cp.async pipeline. 16 warps (4x4), warp tile 32x32.
// smem rows padded to 80B: conflict-free ldmatrix + cp.async.
// ============================================================================
#define GSTG   40960            // bytes per stage: 4 tiles * 128 rows * 80B
#define GSMEM  (3*GSTG)

__global__ __launch_bounds__(512, 1)
void gemm_tc(const __half* __restrict__ Ah, const __half* __restrict__ Al,
             const __half* __restrict__ Bh, const __half* __restrict__ Bl,
             const float* __restrict__ bias, float* __restrict__ outp, int mode)
{
    extern __shared__ char smg[];
    const uint32_t smb = smem_u32(smg);
    const int tid = threadIdx.x, lane = tid & 31, wid = tid >> 5;
    const int wm = wid >> 2, wn = wid & 3;          // 4 x 4 warp grid
    const int m0 = blockIdx.y * 128, n0 = blockIdx.x * 128;

    const __half* srcs[4] = {Ah, Al, Bh, Bl};

    auto issue_stage = [&](int kt, int st) {
        #pragma unroll
        for (int it = 0; it < 4; ++it) {
            int idx = it * 512 + tid;           // 0..2047
            int tile = idx >> 9;                // 0..3
            int t2 = idx & 511;
            int row = t2 >> 2, seg = t2 & 3;    // 128 rows x 4 16B-segs
            int grow = (tile < 2 ? m0 : n0) + row;
            const __half* src = srcs[tile] + (size_t)grow * KDIM + kt * 32 + seg * 8;
            uint32_t dst = smb + st * GSTG + tile * 10240 + row * 80 + seg * 16;
            CPA16(dst, src);
        }
    };

    float acc[2][4][4];
    #pragma unroll
    for (int i = 0; i < 2; i++)
        #pragma unroll
        for (int j = 0; j < 4; j++)
            #pragma unroll
            for (int r = 0; r < 4; r++) acc[i][j][r] = 0.f;

    issue_stage(0, 0); CPC();
    issue_stage(1, 1); CPC();

    const int NK = KDIM / 32;
    for (int kt = 0; kt < NK; ++kt) {
        CPW(1);
        __syncthreads();
        if (kt + 2 < NK) { issue_stage(kt + 2, (kt + 2) % 3); CPC(); }

        const uint32_t base = smb + (kt % 3) * GSTG;
        #pragma unroll
        for (int ks = 0; ks < 2; ++ks) {
            uint32_t a_h[2][4], a_l[2][4];
            const int acol = ks * 16 + ((lane >> 4) << 3);
            #pragma unroll
            for (int i = 0; i < 2; ++i) {
                int r = wm * 32 + i * 16 + (lane & 15);
                uint32_t ad = base + r * 80 + acol * 2;
                LDSM4(a_h[i][0], a_h[i][1], a_h[i][2], a_h[i][3], ad);
                LDSM4(a_l[i][0], a_l[i][1], a_l[i][2], a_l[i][3], ad + 10240);
            }
            const int bcol = ks * 16 + (((lane >> 3) & 1) << 3);
            #pragma unroll
            for (int j = 0; j < 4; ++j) {
                int r = wn * 32 + j * 8 + (lane & 7);
                uint32_t bd = base + 20480 + r * 80 + bcol * 2;
                uint32_t b_h[2], b_l[2];
                LDSM2(b_h[0], b_h[1], bd);
                LDSM2(b_l[0], b_l[1], bd + 10240);
                #pragma unroll
                for (int i = 0; i < 2; ++i) {
                    MMA(acc[i][j], a_h[i], b_h);
                    MMA(acc[i][j], a_l[i], b_h);
                    MMA(acc[i][j], a_h[i], b_l);
                }
            }
        }
    }

    // ---------------- epilogue ----------------
    const int g = lane >> 2, tg = lane & 3;
    if (mode == 0) {
        const int sel = (blockIdx.x * 128) >> 10;    // 0=q 1=k 2=v
        __half* dh = (sel == 0) ? g_qh : (sel == 1) ? g_kh : g_vh;
        __half* dl = (sel == 0) ? g_ql : (sel == 1) ? g_kl : g_vl;
        #pragma unroll
        for (int i = 0; i < 2; ++i) {
            #pragma unroll
            for (int j = 0; j < 4; ++j) {
                int n = n0 + wn * 32 + j * 8 + tg * 2;
                int hh = (n & 1023) >> 6, dd = n & 63;
                float b0 = __ldg(bias + n), b1 = __ldg(bias + n + 1);
                #pragma unroll
                for (int rr = 0; rr < 2; ++rr) {
                    int m = m0 + wm * 32 + i * 16 + g + rr * 8;
                    int bb = m >> 11, ss = m & 2047;
                    float v0 = acc[i][j][rr*2+0] + b0;
                    float v1 = acc[i][j][rr*2+1] + b1;
                    __half h0 = __float2half_rn(v0), h1 = __float2half_rn(v1);
                    size_t o = (((size_t)(bb * NH + hh)) * SEQ + ss) * DH + dd;
                    *(__half2*)&dh[o] = __halves2half2(h0, h1);
                    *(__half2*)&dl[o] = __halves2half2(
                        __float2half_rn(v0 - __half2float(h0)),
                        __float2half_rn(v1 - __half2float(h1)));
                }
            }
        }
    } else {
        #pragma unroll
        for (int i = 0; i < 2; ++i) {
            #pragma unroll
            for (int j = 0; j < 4; ++j) {
                int n = n0 + wn * 32 + j * 8 + tg * 2;
                float b0 = __ldg(bias + n), b1 = __ldg(bias + n + 1);
                #pragma unroll
                for (int rr = 0; rr < 2; ++rr) {
                    int m = m0 + wm * 32 + i * 16 + g + rr * 8;
                    float2 w;
                    w.x = acc[i][j][rr*2+0] + b0;
                    w.y = acc[i][j][rr*2+1] + b1;
                    *(float2*)&outp[(size_t)m * EMBD + n] = w;
                }
            }
        }
    }
}

// ============================================================================
// Flash attention, HMMA fp16-split. CTA = 256 q-rows of one (b,h); 8 warps,
// each owns TWO 16-row blocks (rows w*16 and 128+w*16) -> 2 independent
// MMA chains per warp for tensor-pipe ILP. K/V frags load once, feed both.
// smem half-stride 72 (144B rows): conflict-free ldmatrix (incl. trans).
// ============================================================================
#define QROWS  256
#define QTILE  (QROWS*72)      // halves per Q tile (h or l)
#define KVTILE 4608            // 64*72 halves
#define KVBUF  (4*KVTILE)      // Kh,Kl,Vh,Vl
#define ASMEM  ((2*QTILE + 2*KVBUF) * 2)   // bytes = 147456

__global__ __launch_bounds__(256, 1)
void attn_mma()
{
    extern __shared__ __half smh[];
    const uint32_t smb = smem_u32(smh);
    const int tid = threadIdx.x, lane = tid & 31, w = tid >> 5;
    const int g = lane >> 2, tg = lane & 3;
    const int bh = blockIdx.y;
    const int q0 = blockIdx.x * QROWS;
    const size_t hb = (size_t)bh * SEQ * DH;

    const uint32_t Qh_o = 0, Ql_o = QTILE;
    const uint32_t KV_o = 2 * QTILE;

    // ---- prologue: Q (256 rows, h+l) then KV tiles 0,1
    #pragma unroll
    for (int it = 0; it < 16; ++it) {
        int idx = it * 256 + tid;              // 0..4095
        int tile = idx >> 11;                  // 0: Qh, 1: Ql
        int t2 = idx & 2047;
        int row = t2 >> 3, seg = t2 & 7;
        const __half* src = (tile ? g_ql : g_qh) + hb + (size_t)(q0 + row) * DH + seg * 8;
        CPA16(smb + (tile ? Ql_o : Qh_o) * 2 + (row * 72 + seg * 8) * 2, src);
    }
    const __half* kvsrc[4] = {g_kh, g_kl, g_vh, g_vl};
    auto issue_kv = [&](int kt, int b) {
        #pragma unroll
        for (int it = 0; it < 8; ++it) {
            int idx = it * 256 + tid;          // 0..2047
            int tile = idx >> 9;               // Kh,Kl,Vh,Vl
            int t2 = idx & 511;
            int row = t2 >> 3, seg = t2 & 7;
            const __half* src = kvsrc[tile] + hb + (size_t)(kt * 64 + row) * DH + seg * 8;
            uint32_t dst = smb + (KV_o + b * KVBUF + tile * KVTILE + row * 72 + seg * 8) * 2;
            CPA16(dst, src);
        }
    };
    issue_kv(0, 0); CPC();
    issue_kv(1, 1); CPC();

    float o0[8][4], o1[8][4], m0_[2], m1_[2], l0_[2], l1_[2];
    #pragma unroll
    for (int j = 0; j < 8; j++)
        #pragma unroll
        for (int r = 0; r < 4; r++) { o0[j][r] = 0.f; o1[j][r] = 0.f; }
    m0_[0] = m0_[1] = m1_[0] = m1_[1] = __int_as_float(0xff800000);
    l0_[0] = l0_[1] = l1_[0] = l1_[1] = 0.f;

    const int NT = SEQ / 64;
    for (int kt = 0; kt < NT; ++kt) {
        const int b = kt & 1;
        const uint32_t kvb = KV_o + b * KVBUF;
        CPW(1);
        __syncthreads();

        // ---- S = Q K^T for both row blocks ----
        float s0[8][4], s1[8][4];
        #pragma unroll
        for (int j = 0; j < 8; j++)
            #pragma unroll
            for (int r = 0; r < 4; r++) { s0[j][r] = 0.f; s1[j][r] = 0.f; }

        #pragma unroll
        for (int ds = 0; ds < 4; ++ds) {
            uint32_t qh0[4], ql0[4], qh1[4], ql1[4];
            {
                int col = ds * 16 + ((lane >> 4) << 3);
                int r0 = w * 16 + (lane & 15);
                int r1 = 128 + w * 16 + (lane & 15);
                uint32_t a0 = smb + (r0 * 72 + col) * 2;
                uint32_t a1 = smb + (r1 * 72 + col) * 2;
                LDSM4(qh0[0], qh0[1], qh0[2], qh0[3], a0 + Qh_o * 2);
                LDSM4(ql0[0], ql0[1], ql0[2], ql0[3], a0 + Ql_o * 2);
                LDSM4(qh1[0], qh1[1], qh1[2], qh1[3], a1 + Qh_o * 2);
                LDSM4(ql1[0], ql1[1], ql1[2], ql1[3], a1 + Ql_o * 2);
            }
            int bcol = ds * 16 + (((lane >> 3) & 1) << 3);
            #pragma unroll
            for (int j = 0; j < 8; ++j) {
                int r = j * 8 + (lane & 7);
                uint32_t kd = smb + (kvb + r * 72 + bcol) * 2;
                uint32_t kh2[2], kl2[2];
                LDSM2(kh2[0], kh2[1], kd);
                LDSM2(kl2[0], kl2[1], kd + KVTILE * 2);
                MMA(s0[j], qh0, kh2);
                MMA(s1[j], qh1, kh2);
                MMA(s0[j], ql0, kh2);
                MMA(s1[j], ql1, kh2);
                MMA(s0[j], qh0, kl2);
                MMA(s1[j], qh1, kl2);
            }
        }

        // ---- online softmax for both row blocks ----
        #pragma unroll
        for (int rb = 0; rb < 2; ++rb) {
            float (*s)[4] = rb ? s1 : s0;
            float (*o)[4] = rb ? o1 : o0;
            float* m_ = rb ? m1_ : m0_;
            float* l_ = rb ? l1_ : l0_;
            #pragma unroll
            for (int rr = 0; rr < 2; ++rr) {
                float mx = m_[rr];
                #pragma unroll
                for (int j = 0; j < 8; ++j) {
                    float v0 = s[j][rr*2+0] * 0.125f, v1 = s[j][rr*2+1] * 0.125f;
                    s[j][rr*2+0] = v0; s[j][rr*2+1] = v1;
                    mx = fmaxf(mx, fmaxf(v0, v1));
                }
                mx = fmaxf(mx, __shfl_xor_sync(0xffffffffu, mx, 1));
                mx = fmaxf(mx, __shfl_xor_sync(0xffffffffu, mx, 2));
                float alpha = __expf(m_[rr] - mx);
                m_[rr] = mx;
                float rs = 0.f;
                #pragma unroll
                for (int j = 0; j < 8; ++j) {
                    float e0 = __expf(s[j][rr*2+0] - mx);
                    float e1 = __expf(s[j][rr*2+1] - mx);
                    s[j][rr*2+0] = e0; s[j][rr*2+1] = e1;
                    rs += e0 + e1;
                }
                rs += __shfl_xor_sync(0xffffffffu, rs, 1);
                rs += __shfl_xor_sync(0xffffffffu, rs, 2);
                l_[rr] = l_[rr] * alpha + rs;
                #pragma unroll
                for (int j = 0; j < 8; ++j) {
                    o[j][rr*2+0] *= alpha;
                    o[j][rr*2+1] *= alpha;
                }
            }
        }

        // ---- O += P V (P split in registers, V frags shared by both rb) ----
        #pragma unroll
        for (int ks = 0; ks < 4; ++ks) {
            uint32_t pa0h[4], pa0l[4], pa1h[4], pa1l[4];
            #pragma unroll
            for (int hi = 0; hi < 2; ++hi) {
                float* f0 = s0[ks * 2 + hi];
                float* f1 = s1[ks * 2 + hi];
                #pragma unroll
                for (int q = 0; q < 2; ++q) {
                    float u0 = f0[q*2+0], u1 = f0[q*2+1];
                    float w0 = f1[q*2+0], w1 = f1[q*2+1];
                    __half t0 = __float2half_rn(u0), t1 = __float2half_rn(u1);
                    __half r0 = __float2half_rn(w0), r1 = __float2half_rn(w1);
                    pa0h[hi*2+q] = packh2(u0, u1);
                    pa0l[hi*2+q] = packh2(u0 - __half2float(t0), u1 - __half2float(t1));
                    pa1h[hi*2+q] = packh2(w0, w1);
                    pa1l[hi*2+q] = packh2(w0 - __half2float(r0), w1 - __half2float(r1));
                }
            }
            int vrow = ks * 16 + (lane & 15);
            #pragma unroll
            for (int jn = 0; jn < 8; ++jn) {
                uint32_t vd = smb + (kvb + 2 * KVTILE + vrow * 72 + jn * 8) * 2;
                uint32_t vh2[2], vl2[2];
                LDSM2T(vh2[0], vh2[1], vd);
                LDSM2T(vl2[0], vl2[1], vd + KVTILE * 2);
                MMA(o0[jn], pa0h, vh2);
                MMA(o1[jn], pa1h, vh2);
                MMA(o0[jn], pa0l, vh2);
                MMA(o1[jn], pa1l, vh2);
                MMA(o0[jn], pa0h, vl2);
                MMA(o1[jn], pa1h, vl2);
            }
        }

        __syncthreads();
        if (kt + 2 < NT) { issue_kv(kt + 2, b); CPC(); }
    }

    // ---- epilogue: normalize, split fp16, store to g_ah/g_al (both rbs) ----
    const int bb = bh >> 4, hh = bh & 15;
    #pragma unroll
    for (int rb = 0; rb < 2; ++rb) {
        float (*o)[4] = rb ? o1 : o0;
        float* l_ = rb ? l1_ : l0_;
        #pragma unroll
        for (int rr = 0; rr < 2; ++rr) {
            float inv = 1.0f / l_[rr];
            int sq = q0 + rb * 128 + w * 16 + g + rr * 8;
            size_t rowo = ((size_t)(bb * SEQ + sq)) * EMBD + hh * DH;
            #pragma unroll
            for (int jn = 0; jn < 8; ++jn) {
                int dd = jn * 8 + tg * 2;
                float v0 = o[jn][rr*2+0] * inv;
                float v1 = o[jn][rr*2+1] * inv;
                __half h0 = __float2half_rn(v0), h1 = __float2half_rn(v1);
                *(__half2*)&g_ah[rowo + dd] = __halves2half2(h0, h1);
                *(__half2*)&g_al[rowo + dd] = __halves2half2(
                    __float2half_rn(v0 - __half2float(h0)),
                    __float2half_rn(v1 - __half2float(h1)));
            }
        }
    }
}

// ============================================================================
extern "C" void kernel_launch(void* const* d_in, const int* in_sizes, int n_in,
                              void* d_out, int out_size)
{
    const float* x     = (const float*)d_in[0];
    const float* W_in  = (const float*)d_in[1];
    const float* b_in  = (const float*)d_in[2];
    const float* W_out = (const float*)d_in[3];
    const float* b_out = (const float*)d_in[4];
    float* out = (float*)d_out;

    cudaFuncSetAttribute(gemm_tc, cudaFuncAttributeMaxDynamicSharedMemorySize, GSMEM);
    cudaFuncSetAttribute(attn_mma, cudaFuncAttributeMaxDynamicSharedMemorySize, ASMEM);

    __half *xh, *xl, *wih, *wil, *woh, *wol, *ah, *al;
    cudaGetSymbolAddress((void**)&xh,  g_xh);
    cudaGetSymbolAddress((void**)&xl,  g_xl);
    cudaGetSymbolAddress((void**)&wih, g_wih);
    cudaGetSymbolAddress((void**)&wil, g_wil);
    cudaGetSymbolAddress((void**)&woh, g_woh);
    cudaGetSymbolAddress((void**)&wol, g_wol);
    cudaGetSymbolAddress((void**)&ah,  g_ah);
    cudaGetSymbolAddress((void**)&al,  g_al);

    // fp32 -> fp16 hi/lo splits
    cvt_kernel<<<(MROWS*KDIM/4)/256, 256>>>(x, xh, xl, MROWS*KDIM/4);
    cvt_kernel<<<(3*EMBD*KDIM/4)/256, 256>>>(W_in, wih, wil, 3*EMBD*KDIM/4);
    cvt_kernel<<<(EMBD*KDIM/4)/256, 256>>>(W_out, woh, wol, EMBD*KDIM/4);

    // QKV: [4096,3072] = X @ W_in^T + b_in -> split-scatter q/k/v (hi,lo)
    gemm_tc<<<dim3(3072/128, MROWS/128), 512, GSMEM>>>(xh, xl, wih, wil, b_in, nullptr, 0);

    // flash attention (HMMA, split, 2 row-blocks per warp)
    attn_mma<<<dim3(SEQ/QROWS, BATCH*NH), 256, ASMEM>>>();

    // out-proj: [4096,1024] = Attn @ W_out^T + b_out
    gemm_tc<<<dim3(EMBD/128, MROWS/128), 512, GSMEM>>>(ah, al, woh, wol, b_out, out, 1);
}

// round 10
// speedup vs baseline: 3.6502x; 1.3580x over previous
#include <cuda_runtime.h>
#include <cuda_fp16.h>
#include <cstdint>

#define EMBD  1024
#define NH    16
#define DH    64
#define BATCH 2
#define SEQ   2048
#define MROWS 4096
#define KDIM  1024

// ---------------- scratch (device globals: allocation-free) ----------------
__device__ __align__(16) __half g_xh[MROWS*KDIM];
__device__ __align__(16) __half g_xl[MROWS*KDIM];
__device__ __align__(16) __half g_wih[3*EMBD*KDIM];
__device__ __align__(16) __half g_woh[EMBD*KDIM];
__device__ __align__(16) __half g_qh[BATCH*NH*SEQ*DH];
__device__ __align__(16) __half g_ql[BATCH*NH*SEQ*DH];
__device__ __align__(16) __half g_kh[BATCH*NH*SEQ*DH];
__device__ __align__(16) __half g_vh[BATCH*NH*SEQ*DH];
__device__ __align__(16) __half g_ah[MROWS*EMBD];
__device__ __align__(16) __half g_al[MROWS*EMBD];

// ---------------- PTX helpers (sm_80-level: valid under compute_103) -------
__device__ __forceinline__ uint32_t smem_u32(const void* p) {
    uint32_t a;
    asm("{ .reg .u64 t; cvta.to.shared.u64 t, %1; cvt.u32.u64 %0, t; }" : "=r"(a) : "l"(p));
    return a;
}
#define CPA16(dst, src) asm volatile("cp.async.cg.shared.global [%0], [%1], 16;" :: "r"(dst), "l"(src))
#define CPC()   asm volatile("cp.async.commit_group;" ::: "memory")
#define CPW(n)  asm volatile("cp.async.wait_group %0;" :: "n"(n) : "memory")

#define LDSM4(r0,r1,r2,r3,a) \
    asm volatile("ldmatrix.sync.aligned.m8n8.x4.shared.b16 {%0,%1,%2,%3}, [%4];" \
        : "=r"(r0),"=r"(r1),"=r"(r2),"=r"(r3) : "r"(a))
#define LDSM2(r0,r1,a) \
    asm volatile("ldmatrix.sync.aligned.m8n8.x2.shared.b16 {%0,%1}, [%2];" \
        : "=r"(r0),"=r"(r1) : "r"(a))
#define LDSM2T(r0,r1,a) \
    asm volatile("ldmatrix.sync.aligned.m8n8.x2.trans.shared.b16 {%0,%1}, [%2];" \
        : "=r"(r0),"=r"(r1) : "r"(a))

#define MMA(d, a, b) \
    asm volatile("mma.sync.aligned.m16n8k16.row.col.f32.f16.f16.f32 " \
        "{%0,%1,%2,%3},{%4,%5,%6,%7},{%8,%9},{%0,%1,%2,%3};" \
        : "+f"((d)[0]),"+f"((d)[1]),"+f"((d)[2]),"+f"((d)[3]) \
        : "r"((a)[0]),"r"((a)[1]),"r"((a)[2]),"r"((a)[3]),"r"((b)[0]),"r"((b)[1]))

__device__ __forceinline__ uint32_t packh2(float a, float b) {
    __half2 h = __halves2half2(__float2half_rn(a), __float2half_rn(b));
    return *reinterpret_cast<uint32_t*>(&h);
}

// ---------------- fp32 -> fp16 hi/lo split ----------------
__global__ __launch_bounds__(256)
void cvt_kernel(const float* __restrict__ s, __half* __restrict__ hi,
                __half* __restrict__ lo, int n4)
{
    int i = blockIdx.x * 256 + threadIdx.x;
    if (i >= n4) return;
    float4 v = ((const float4*)s)[i];
    __half h0 = __float2half_rn(v.x), h1 = __float2half_rn(v.y);
    __half h2 = __float2half_rn(v.z), h3 = __float2half_rn(v.w);
    ((__half2*)hi)[2*i]   = __halves2half2(h0, h1);
    ((__half2*)hi)[2*i+1] = __halves2half2(h2, h3);
    ((__half2*)lo)[2*i]   = __halves2half2(
        __float2half_rn(v.x - __half2float(h0)), __float2half_rn(v.y - __half2float(h1)));
    ((__half2*)lo)[2*i+1] = __halves2half2(
        __float2half_rn(v.z - __half2float(h2)), __float2half_rn(v.w - __half2float(h3)));
}

// hi-only convert (weights: B-side low bits dropped by the 2-term scheme)
__global__ __launch_bounds__(256)
void cvt_hi_kernel(const float* __restrict__ s, __half* __restrict__ hi, int n4)
{
    int i = blockIdx.x * 256 + threadIdx.x;
    if (i >= n4) return;
    float4 v = ((const float4*)s)[i];
    ((__half2*)hi)[2*i]   = __halves2half2(__float2half_rn(v.x), __float2half_rn(v.y));
    ((__half2*)hi)[2*i+1] = __halves2half2(__float2half_rn(v.z), __float2half_rn(v.w));
}

// ============================================================================
// HMMA NT GEMM (2-term split): C = (Ah+Al)[M,K] * Bh[N,K]^T, K=1024.
// BK=32, 3-stage cp.async pipeline. 16 warps (4x4), warp tile 32x32.
// Stage tiles: Ah, Al, Bh (3 x 128 rows x 80B).
// ============================================================================
#define GSTG   30720            // bytes per stage: 3 tiles * 128 rows * 80B
#define GSMEM  (3*GSTG)

__global__ __launch_bounds__(512, 1)
void gemm_tc(const __half* __restrict__ Ah, const __half* __restrict__ Al,
             const __half* __restrict__ Bh,
             const float* __restrict__ bias, float* __restrict__ outp, int mode)
{
    extern __shared__ char smg[];
    const uint32_t smb = smem_u32(smg);
    const int tid = threadIdx.x, lane = tid & 31, wid = tid >> 5;
    const int wm = wid >> 2, wn = wid & 3;          // 4 x 4 warp grid
    const int m0 = blockIdx.y * 128, n0 = blockIdx.x * 128;

    const __half* srcs[3] = {Ah, Al, Bh};

    auto issue_stage = [&](int kt, int st) {
        #pragma unroll
        for (int it = 0; it < 3; ++it) {
            int idx = it * 512 + tid;           // 0..1535
            int tile = idx >> 9;                // 0..2
            int t2 = idx & 511;
            int row = t2 >> 2, seg = t2 & 3;    // 128 rows x 4 16B-segs
            int grow = (tile < 2 ? m0 : n0) + row;
            const __half* src = srcs[tile] + (size_t)grow * KDIM + kt * 32 + seg * 8;
            uint32_t dst = smb + st * GSTG + tile * 10240 + row * 80 + seg * 16;
            CPA16(dst, src);
        }
    };

    float acc[2][4][4];
    #pragma unroll
    for (int i = 0; i < 2; i++)
        #pragma unroll
        for (int j = 0; j < 4; j++)
            #pragma unroll
            for (int r = 0; r < 4; r++) acc[i][j][r] = 0.f;

    issue_stage(0, 0); CPC();
    issue_stage(1, 1); CPC();

    const int NK = KDIM / 32;
    for (int kt = 0; kt < NK; ++kt) {
        CPW(1);
        __syncthreads();
        if (kt + 2 < NK) { issue_stage(kt + 2, (kt + 2) % 3); CPC(); }

        const uint32_t base = smb + (kt % 3) * GSTG;
        #pragma unroll
        for (int ks = 0; ks < 2; ++ks) {
            uint32_t a_h[2][4], a_l[2][4];
            const int acol = ks * 16 + ((lane >> 4) << 3);
            #pragma unroll
            for (int i = 0; i < 2; ++i) {
                int r = wm * 32 + i * 16 + (lane & 15);
                uint32_t ad = base + r * 80 + acol * 2;
                LDSM4(a_h[i][0], a_h[i][1], a_h[i][2], a_h[i][3], ad);
                LDSM4(a_l[i][0], a_l[i][1], a_l[i][2], a_l[i][3], ad + 10240);
            }
            const int bcol = ks * 16 + (((lane >> 3) & 1) << 3);
            #pragma unroll
            for (int j = 0; j < 4; ++j) {
                int r = wn * 32 + j * 8 + (lane & 7);
                uint32_t bd = base + 20480 + r * 80 + bcol * 2;
                uint32_t b_h[2];
                LDSM2(b_h[0], b_h[1], bd);
                #pragma unroll
                for (int i = 0; i < 2; ++i) {
                    MMA(acc[i][j], a_h[i], b_h);
                    MMA(acc[i][j], a_l[i], b_h);
                }
            }
        }
    }

    // ---------------- epilogue ----------------
    const int g = lane >> 2, tg = lane & 3;
    if (mode == 0) {
        const int sel = (blockIdx.x * 128) >> 10;    // 0=q 1=k 2=v
        __half* dh = (sel == 0) ? g_qh : (sel == 1) ? g_kh : g_vh;
        #pragma unroll
        for (int i = 0; i < 2; ++i) {
            #pragma unroll
            for (int j = 0; j < 4; ++j) {
                int n = n0 + wn * 32 + j * 8 + tg * 2;
                int hh = (n & 1023) >> 6, dd = n & 63;
                float b0 = __ldg(bias + n), b1 = __ldg(bias + n + 1);
                #pragma unroll
                for (int rr = 0; rr < 2; ++rr) {
                    int m = m0 + wm * 32 + i * 16 + g + rr * 8;
                    int bb = m >> 11, ss = m & 2047;
                    float v0 = acc[i][j][rr*2+0] + b0;
                    float v1 = acc[i][j][rr*2+1] + b1;
                    __half h0 = __float2half_rn(v0), h1 = __float2half_rn(v1);
                    size_t o = (((size_t)(bb * NH + hh)) * SEQ + ss) * DH + dd;
                    *(__half2*)&dh[o] = __halves2half2(h0, h1);
                    if (sel == 0)   // only Q keeps low bits (A-side of QK^T)
                        *(__half2*)&g_ql[o] = __halves2half2(
                            __float2half_rn(v0 - __half2float(h0)),
                            __float2half_rn(v1 - __half2float(h1)));
                }
            }
        }
    } else {
        #pragma unroll
        for (int i = 0; i < 2; ++i) {
            #pragma unroll
            for (int j = 0; j < 4; ++j) {
                int n = n0 + wn * 32 + j * 8 + tg * 2;
                float b0 = __ldg(bias + n), b1 = __ldg(bias + n + 1);
                #pragma unroll
                for (int rr = 0; rr < 2; ++rr) {
                    int m = m0 + wm * 32 + i * 16 + g + rr * 8;
                    float2 w;
                    w.x = acc[i][j][rr*2+0] + b0;
                    w.y = acc[i][j][rr*2+1] + b1;
                    *(float2*)&outp[(size_t)m * EMBD + n] = w;
                }
            }
        }
    }
}

// ============================================================================
// Flash attention, HMMA 2-term split. CTA = 256 q-rows of one (b,h); 8 warps,
// each owns TWO 16-row blocks -> 2 independent MMA chains per warp.
// S = (Qh+Ql)Kh^T ; O += (Ph+Pl)Vh.  K/V low parts dropped (O(eps) error).
// smem half-stride 72 (144B rows): conflict-free ldmatrix (incl. trans).
// ============================================================================
#define QROWS  256
#define QTILE  (QROWS*72)      // halves per Q tile (h or l)
#define KVTILE 4608            // 64*72 halves
#define KVBUF  (2*KVTILE)      // Kh, Vh
#define ASMEM  ((2*QTILE + 2*KVBUF) * 2)   // bytes = 110592

__global__ __launch_bounds__(256, 1)
void attn_mma()
{
    extern __shared__ __half smh[];
    const uint32_t smb = smem_u32(smh);
    const int tid = threadIdx.x, lane = tid & 31, w = tid >> 5;
    const int g = lane >> 2, tg = lane & 3;
    const int bh = blockIdx.y;
    const int q0 = blockIdx.x * QROWS;
    const size_t hb = (size_t)bh * SEQ * DH;

    const uint32_t Qh_o = 0, Ql_o = QTILE;
    const uint32_t KV_o = 2 * QTILE;

    // ---- prologue: Q (256 rows, h+l) then KV tiles 0,1
    #pragma unroll
    for (int it = 0; it < 16; ++it) {
        int idx = it * 256 + tid;              // 0..4095
        int tile = idx >> 11;                  // 0: Qh, 1: Ql
        int t2 = idx & 2047;
        int row = t2 >> 3, seg = t2 & 7;
        const __half* src = (tile ? g_ql : g_qh) + hb + (size_t)(q0 + row) * DH + seg * 8;
        CPA16(smb + (tile ? Ql_o : Qh_o) * 2 + (row * 72 + seg * 8) * 2, src);
    }
    const __half* kvsrc[2] = {g_kh, g_vh};
    auto issue_kv = [&](int kt, int b) {
        #pragma unroll
        for (int it = 0; it < 4; ++it) {
            int idx = it * 256 + tid;          // 0..1023
            int tile = idx >> 9;               // 0: Kh, 1: Vh
            int t2 = idx & 511;
            int row = t2 >> 3, seg = t2 & 7;
            const __half* src = kvsrc[tile] + hb + (size_t)(kt * 64 + row) * DH + seg * 8;
            uint32_t dst = smb + (KV_o + b * KVBUF + tile * KVTILE + row * 72 + seg * 8) * 2;
            CPA16(dst, src);
        }
    };
    issue_kv(0, 0); CPC();
    issue_kv(1, 1); CPC();

    float o0[8][4], o1[8][4], m0_[2], m1_[2], l0_[2], l1_[2];
    #pragma unroll
    for (int j = 0; j < 8; j++)
        #pragma unroll
        for (int r = 0; r < 4; r++) { o0[j][r] = 0.f; o1[j][r] = 0.f; }
    m0_[0] = m0_[1] = m1_[0] = m1_[1] = __int_as_float(0xff800000);
    l0_[0] = l0_[1] = l1_[0] = l1_[1] = 0.f;

    const int NT = SEQ / 64;
    for (int kt = 0; kt < NT; ++kt) {
        const int b = kt & 1;
        const uint32_t kvb = KV_o + b * KVBUF;
        CPW(1);
        __syncthreads();

        // ---- S = Q K^T for both row blocks ----
        float s0[8][4], s1[8][4];
        #pragma unroll
        for (int j = 0; j < 8; j++)
            #pragma unroll
            for (int r = 0; r < 4; r++) { s0[j][r] = 0.f; s1[j][r] = 0.f; }

        #pragma unroll
        for (int ds = 0; ds < 4; ++ds) {
            uint32_t qh0[4], ql0[4], qh1[4], ql1[4];
            {
                int col = ds * 16 + ((lane >> 4) << 3);
                int r0 = w * 16 + (lane & 15);
                int r1 = 128 + w * 16 + (lane & 15);
                uint32_t a0 = smb + (r0 * 72 + col) * 2;
                uint32_t a1 = smb + (r1 * 72 + col) * 2;
                LDSM4(qh0[0], qh0[1], qh0[2], qh0[3], a0 + Qh_o * 2);
                LDSM4(ql0[0], ql0[1], ql0[2], ql0[3], a0 + Ql_o * 2);
                LDSM4(qh1[0], qh1[1], qh1[2], qh1[3], a1 + Qh_o * 2);
                LDSM4(ql1[0], ql1[1], ql1[2], ql1[3], a1 + Ql_o * 2);
            }
            int bcol = ds * 16 + (((lane >> 3) & 1) << 3);
            #pragma unroll
            for (int j = 0; j < 8; ++j) {
                int r = j * 8 + (lane & 7);
                uint32_t kd = smb + (kvb + r * 72 + bcol) * 2;
                uint32_t kh2[2];
                LDSM2(kh2[0], kh2[1], kd);
                MMA(s0[j], qh0, kh2);
                MMA(s1[j], qh1, kh2);
                MMA(s0[j], ql0, kh2);
                MMA(s1[j], ql1, kh2);
            }
        }

        // ---- online softmax for both row blocks ----
        #pragma unroll
        for (int rb = 0; rb < 2; ++rb) {
            float (*s)[4] = rb ? s1 : s0;
            float (*o)[4] = rb ? o1 : o0;
            float* m_ = rb ? m1_ : m0_;
            float* l_ = rb ? l1_ : l0_;
            #pragma unroll
            for (int rr = 0; rr < 2; ++rr) {
                float mx = m_[rr];
                #pragma unroll
                for (int j = 0; j < 8; ++j) {
                    float v0 = s[j][rr*2+0] * 0.125f, v1 = s[j][rr*2+1] * 0.125f;
                    s[j][rr*2+0] = v0; s[j][rr*2+1] = v1;
                    mx = fmaxf(mx, fmaxf(v0, v1));
                }
                mx = fmaxf(mx, __shfl_xor_sync(0xffffffffu, mx, 1));
                mx = fmaxf(mx, __shfl_xor_sync(0xffffffffu, mx, 2));
                float alpha = __expf(m_[rr] - mx);
                m_[rr] = mx;
                float rs = 0.f;
                #pragma unroll
                for (int j = 0; j < 8; ++j) {
                    float e0 = __expf(s[j][rr*2+0] - mx);
                    float e1 = __expf(s[j][rr*2+1] - mx);
                    s[j][rr*2+0] = e0; s[j][rr*2+1] = e1;
                    rs += e0 + e1;
                }
                rs += __shfl_xor_sync(0xffffffffu, rs, 1);
                rs += __shfl_xor_sync(0xffffffffu, rs, 2);
                l_[rr] = l_[rr] * alpha + rs;
                #pragma unroll
                for (int j = 0; j < 8; ++j) {
                    o[j][rr*2+0] *= alpha;
                    o[j][rr*2+1] *= alpha;
                }
            }
        }

        // ---- O += P V (P split in registers, Vh from smem) ----
        #pragma unroll
        for (int ks = 0; ks < 4; ++ks) {
            uint32_t pa0h[4], pa0l[4], pa1h[4], pa1l[4];
            #pragma unroll
            for (int hi = 0; hi < 2; ++hi) {
                float* f0 = s0[ks * 2 + hi];
                float* f1 = s1[ks * 2 + hi];
                #pragma unroll
                for (int q = 0; q < 2; ++q) {
                    float u0 = f0[q*2+0], u1 = f0[q*2+1];
                    float w0 = f1[q*2+0], w1 = f1[q*2+1];
                    __half t0 = __float2half_rn(u0), t1 = __float2half_rn(u1);
                    __half r0 = __float2half_rn(w0), r1 = __float2half_rn(w1);
                    pa0h[hi*2+q] = packh2(u0, u1);
                    pa0l[hi*2+q] = packh2(u0 - __half2float(t0), u1 - __half2float(t1));
                    pa1h[hi*2+q] = packh2(w0, w1);
                    pa1l[hi*2+q] = packh2(w0 - __half2float(r0), w1 - __half2float(r1));
                }
            }
            int vrow = ks * 16 + (lane & 15);
            #pragma unroll
            for (int jn = 0; jn < 8; ++jn) {
                uint32_t vd = smb + (kvb + KVTILE + vrow * 72 + jn * 8) * 2;
                uint32_t vh2[2];
                LDSM2T(vh2[0], vh2[1], vd);
                MMA(o0[jn], pa0h, vh2);
                MMA(o1[jn], pa1h, vh2);
                MMA(o0[jn], pa0l, vh2);
                MMA(o1[jn], pa1l, vh2);
            }
        }

        __syncthreads();
        if (kt + 2 < NT) { issue_kv(kt + 2, b); CPC(); }
    }

    // ---- epilogue: normalize, split fp16, store to g_ah/g_al (both rbs) ----
    const int bb = bh >> 4, hh = bh & 15;
    #pragma unroll
    for (int rb = 0; rb < 2; ++rb) {
        float (*o)[4] = rb ? o1 : o0;
        float* l_ = rb ? l1_ : l0_;
        #pragma unroll
        for (int rr = 0; rr < 2; ++rr) {
            float inv = 1.0f / l_[rr];
            int sq = q0 + rb * 128 + w * 16 + g + rr * 8;
            size_t rowo = ((size_t)(bb * SEQ + sq)) * EMBD + hh * DH;
            #pragma unroll
            for (int jn = 0; jn < 8; ++jn) {
                int dd = jn * 8 + tg * 2;
                float v0 = o[jn][rr*2+0] * inv;
                float v1 = o[jn][rr*2+1] * inv;
                __half h0 = __float2half_rn(v0), h1 = __float2half_rn(v1);
                *(__half2*)&g_ah[rowo + dd] = __halves2half2(h0, h1);
                *(__half2*)&g_al[rowo + dd] = __halves2half2(
                    __float2half_rn(v0 - __half2float(h0)),
                    __float2half_rn(v1 - __half2float(h1)));
            }
        }
    }
}

// ============================================================================
extern "C" void kernel_launch(void* const* d_in, const int* in_sizes, int n_in,
                              void* d_out, int out_size)
{
    const float* x     = (const float*)d_in[0];
    const float* W_in  = (const float*)d_in[1];
    const float* b_in  = (const float*)d_in[2];
    const float* W_out = (const float*)d_in[3];
    const float* b_out = (const float*)d_in[4];
    float* out = (float*)d_out;

    cudaFuncSetAttribute(gemm_tc, cudaFuncAttributeMaxDynamicSharedMemorySize, GSMEM);
    cudaFuncSetAttribute(attn_mma, cudaFuncAttributeMaxDynamicSharedMemorySize, ASMEM);

    __half *xh, *xl, *wih, *woh, *ah, *al;
    cudaGetSymbolAddress((void**)&xh,  g_xh);
    cudaGetSymbolAddress((void**)&xl,  g_xl);
    cudaGetSymbolAddress((void**)&wih, g_wih);
    cudaGetSymbolAddress((void**)&woh, g_woh);
    cudaGetSymbolAddress((void**)&ah,  g_ah);
    cudaGetSymbolAddress((void**)&al,  g_al);

    // fp32 -> fp16 splits: x full (hi+lo), weights hi-only
    cvt_kernel<<<(MROWS*KDIM/4)/256, 256>>>(x, xh, xl, MROWS*KDIM/4);
    cvt_hi_kernel<<<(3*EMBD*KDIM/4)/256, 256>>>(W_in, wih, 3*EMBD*KDIM/4);
    cvt_hi_kernel<<<(EMBD*KDIM/4)/256, 256>>>(W_out, woh, EMBD*KDIM/4);

    // QKV: [4096,3072] = X @ W_in^T + b_in -> scatter q(h,l)/k(h)/v(h)
    gemm_tc<<<dim3(3072/128, MROWS/128), 512, GSMEM>>>(xh, xl, wih, b_in, nullptr, 0);

    // flash attention (HMMA, 2-term split, 2 row-blocks per warp)
    attn_mma<<<dim3(SEQ/QROWS, BATCH*NH), 256, ASMEM>>>();

    // out-proj: [4096,1024] = Attn @ W_out^T + b_out
    gemm_tc<<<dim3(EMBD/128, MROWS/128), 512, GSMEM>>>(ah, al, woh, b_out, out, 1);
}

// round 11
// speedup vs baseline: 3.9333x; 1.0776x over previous
#include <cuda_runtime.h>
#include <cuda_fp16.h>
#include <cstdint>

#define EMBD  1024
#define NH    16
#define DH    64
#define BATCH 2
#define SEQ   2048
#define MROWS 4096
#define KDIM  1024

// ---------------- scratch (device globals: allocation-free) ----------------
__device__ __align__(16) __half g_xh[MROWS*KDIM];
__device__ __align__(16) __half g_xl[MROWS*KDIM];
__device__ __align__(16) __half g_wih[3*EMBD*KDIM];
__device__ __align__(16) __half g_woh[EMBD*KDIM];
__device__ __align__(16) __half g_qh[BATCH*NH*SEQ*DH];
__device__ __align__(16) __half g_ql[BATCH*NH*SEQ*DH];
__device__ __align__(16) __half g_kh[BATCH*NH*SEQ*DH];
__device__ __align__(16) __half g_vh[BATCH*NH*SEQ*DH];
__device__ __align__(16) __half g_ah[MROWS*EMBD];
__device__ __align__(16) __half g_al[MROWS*EMBD];

// ---------------- PTX helpers (sm_80-level: valid under compute_103) -------
__device__ __forceinline__ uint32_t smem_u32(const void* p) {
    uint32_t a;
    asm("{ .reg .u64 t; cvta.to.shared.u64 t, %1; cvt.u32.u64 %0, t; }" : "=r"(a) : "l"(p));
    return a;
}
#define CPA16(dst, src) asm volatile("cp.async.cg.shared.global [%0], [%1], 16;" :: "r"(dst), "l"(src))
#define CPC()   asm volatile("cp.async.commit_group;" ::: "memory")
#define CPW(n)  asm volatile("cp.async.wait_group %0;" :: "n"(n) : "memory")

#define LDSM4(r0,r1,r2,r3,a) \
    asm volatile("ldmatrix.sync.aligned.m8n8.x4.shared.b16 {%0,%1,%2,%3}, [%4];" \
        : "=r"(r0),"=r"(r1),"=r"(r2),"=r"(r3) : "r"(a))
#define LDSM2(r0,r1,a) \
    asm volatile("ldmatrix.sync.aligned.m8n8.x2.shared.b16 {%0,%1}, [%2];" \
        : "=r"(r0),"=r"(r1) : "r"(a))
#define LDSM2T(r0,r1,a) \
    asm volatile("ldmatrix.sync.aligned.m8n8.x2.trans.shared.b16 {%0,%1}, [%2];" \
        : "=r"(r0),"=r"(r1) : "r"(a))

#define MMA(d, a, b) \
    asm volatile("mma.sync.aligned.m16n8k16.row.col.f32.f16.f16.f32 " \
        "{%0,%1,%2,%3},{%4,%5,%6,%7},{%8,%9},{%0,%1,%2,%3};" \
        : "+f"((d)[0]),"+f"((d)[1]),"+f"((d)[2]),"+f"((d)[3]) \
        : "r"((a)[0]),"r"((a)[1]),"r"((a)[2]),"r"((a)[3]),"r"((b)[0]),"r"((b)[1]))

__device__ __forceinline__ uint32_t packh2(float a, float b) {
    __half2 h = __halves2half2(__float2half_rn(a), __float2half_rn(b));
    return *reinterpret_cast<uint32_t*>(&h);
}

// ---------------- fp32 -> fp16 hi/lo split ----------------
__global__ __launch_bounds__(256)
void cvt_kernel(const float* __restrict__ s, __half* __restrict__ hi,
                __half* __restrict__ lo, int n4)
{
    int i = blockIdx.x * 256 + threadIdx.x;
    if (i >= n4) return;
    float4 v = ((const float4*)s)[i];
    __half h0 = __float2half_rn(v.x), h1 = __float2half_rn(v.y);
    __half h2 = __float2half_rn(v.z), h3 = __float2half_rn(v.w);
    ((__half2*)hi)[2*i]   = __halves2half2(h0, h1);
    ((__half2*)hi)[2*i+1] = __halves2half2(h2, h3);
    ((__half2*)lo)[2*i]   = __halves2half2(
        __float2half_rn(v.x - __half2float(h0)), __float2half_rn(v.y - __half2float(h1)));
    ((__half2*)lo)[2*i+1] = __halves2half2(
        __float2half_rn(v.z - __half2float(h2)), __float2half_rn(v.w - __half2float(h3)));
}

__global__ __launch_bounds__(256)
void cvt_hi_kernel(const float* __restrict__ s, __half* __restrict__ hi, int n4)
{
    int i = blockIdx.x * 256 + threadIdx.x;
    if (i >= n4) return;
    float4 v = ((const float4*)s)[i];
    ((__half2*)hi)[2*i]   = __halves2half2(__float2half_rn(v.x), __float2half_rn(v.y));
    ((__half2*)hi)[2*i+1] = __halves2half2(__float2half_rn(v.z), __float2half_rn(v.w));
}

// ============================================================================
// HMMA NT GEMM (2-term split): C = (Ah+Al)[M,K] * Bh[N,K]^T, K=1024.
// BK=64 (barrier amortization), 3-stage cp.async pipeline. 16 warps (4x4),
// warp tile 32x32. Rows 64 halves data + 8 pad = 144B (conflict-free).
// ============================================================================
#define GROW   144              // bytes per smem row
#define GTILE  (128*GROW)       // 18432 B per tile
#define GSTG   (3*GTILE)        // 55296 B per stage (Ah, Al, Bh)
#define GSMEM  (3*GSTG)         // 165888 B

__global__ __launch_bounds__(512, 1)
void gemm_tc(const __half* __restrict__ Ah, const __half* __restrict__ Al,
             const __half* __restrict__ Bh,
             const float* __restrict__ bias, float* __restrict__ outp, int mode)
{
    extern __shared__ char smg[];
    const uint32_t smb = smem_u32(smg);
    const int tid = threadIdx.x, lane = tid & 31, wid = tid >> 5;
    const int wm = wid >> 2, wn = wid & 3;          // 4 x 4 warp grid
    const int m0 = blockIdx.y * 128, n0 = blockIdx.x * 128;

    const __half* srcs[3] = {Ah, Al, Bh};

    auto issue_stage = [&](int kt, int st) {
        #pragma unroll
        for (int it = 0; it < 6; ++it) {
            int idx = it * 512 + tid;           // 0..3071
            int tile = idx >> 10;               // 0..2
            int t2 = idx & 1023;
            int row = t2 >> 3, seg = t2 & 7;    // 128 rows x 8 16B-segs
            int grow = (tile < 2 ? m0 : n0) + row;
            const __half* src = srcs[tile] + (size_t)grow * KDIM + kt * 64 + seg * 8;
            uint32_t dst = smb + st * GSTG + tile * GTILE + row * GROW + seg * 16;
            CPA16(dst, src);
        }
    };

    float acc[2][4][4];
    #pragma unroll
    for (int i = 0; i < 2; i++)
        #pragma unroll
        for (int j = 0; j < 4; j++)
            #pragma unroll
            for (int r = 0; r < 4; r++) acc[i][j][r] = 0.f;

    issue_stage(0, 0); CPC();
    issue_stage(1, 1); CPC();

    const int NK = KDIM / 64;
    for (int kt = 0; kt < NK; ++kt) {
        CPW(1);
        __syncthreads();
        if (kt + 2 < NK) { issue_stage(kt + 2, (kt + 2) % 3); CPC(); }

        const uint32_t base = smb + (kt % 3) * GSTG;
        #pragma unroll
        for (int ks = 0; ks < 4; ++ks) {
            uint32_t a_h[2][4], a_l[2][4];
            const int acol = ks * 16 + ((lane >> 4) << 3);
            #pragma unroll
            for (int i = 0; i < 2; ++i) {
                int r = wm * 32 + i * 16 + (lane & 15);
                uint32_t ad = base + r * GROW + acol * 2;
                LDSM4(a_h[i][0], a_h[i][1], a_h[i][2], a_h[i][3], ad);
                LDSM4(a_l[i][0], a_l[i][1], a_l[i][2], a_l[i][3], ad + GTILE);
            }
            const int bcol = ks * 16 + (((lane >> 3) & 1) << 3);
            #pragma unroll
            for (int j = 0; j < 4; ++j) {
                int r = wn * 32 + j * 8 + (lane & 7);
                uint32_t bd = base + 2 * GTILE + r * GROW + bcol * 2;
                uint32_t b_h[2];
                LDSM2(b_h[0], b_h[1], bd);
                #pragma unroll
                for (int i = 0; i < 2; ++i) {
                    MMA(acc[i][j], a_h[i], b_h);
                    MMA(acc[i][j], a_l[i], b_h);
                }
            }
        }
    }

    // ---------------- epilogue ----------------
    const int g = lane >> 2, tg = lane & 3;
    if (mode == 0) {
        const int sel = (blockIdx.x * 128) >> 10;    // 0=q 1=k 2=v
        __half* dh = (sel == 0) ? g_qh : (sel == 1) ? g_kh : g_vh;
        #pragma unroll
        for (int i = 0; i < 2; ++i) {
            #pragma unroll
            for (int j = 0; j < 4; ++j) {
                int n = n0 + wn * 32 + j * 8 + tg * 2;
                int hh = (n & 1023) >> 6, dd = n & 63;
                float b0 = __ldg(bias + n), b1 = __ldg(bias + n + 1);
                #pragma unroll
                for (int rr = 0; rr < 2; ++rr) {
                    int m = m0 + wm * 32 + i * 16 + g + rr * 8;
                    int bb = m >> 11, ss = m & 2047;
                    float v0 = acc[i][j][rr*2+0] + b0;
                    float v1 = acc[i][j][rr*2+1] + b1;
                    __half h0 = __float2half_rn(v0), h1 = __float2half_rn(v1);
                    size_t o = (((size_t)(bb * NH + hh)) * SEQ + ss) * DH + dd;
                    *(__half2*)&dh[o] = __halves2half2(h0, h1);
                    if (sel == 0)   // only Q keeps low bits (A-side of QK^T)
                        *(__half2*)&g_ql[o] = __halves2half2(
                            __float2half_rn(v0 - __half2float(h0)),
                            __float2half_rn(v1 - __half2float(h1)));
                }
            }
        }
    } else {
        #pragma unroll
        for (int i = 0; i < 2; ++i) {
            #pragma unroll
            for (int j = 0; j < 4; ++j) {
                int n = n0 + wn * 32 + j * 8 + tg * 2;
                float b0 = __ldg(bias + n), b1 = __ldg(bias + n + 1);
                #pragma unroll
                for (int rr = 0; rr < 2; ++rr) {
                    int m = m0 + wm * 32 + i * 16 + g + rr * 8;
                    float2 w;
                    w.x = acc[i][j][rr*2+0] + b0;
                    w.y = acc[i][j][rr*2+1] + b1;
                    *(float2*)&outp[(size_t)m * EMBD + n] = w;
                }
            }
        }
    }
}

// ============================================================================
// Flash attention, HMMA 2-term split. CTA = 256 q-rows of one (b,h); 8 warps,
// each owns TWO 16-row blocks -> 2 independent MMA chains per warp.
// KV staged 128 rows per cp.async stage (2 x 64-row passes per barrier pair).
// S = (Qh+Ql)Kh^T ; O += (Ph+Pl)Vh.
// smem half-stride 72 (144B rows): conflict-free ldmatrix (incl. trans).
// ============================================================================
#define QROWS  256
#define QTILE  (QROWS*72)      // halves per Q tile (h or l)
#define KVHALF 4608            // 64*72 halves (one 64-row sub-tile)
#define KVTILE (2*KVHALF)      // 128*72 halves per K or V tile
#define KVBUF  (2*KVTILE)      // Kh, Vh
#define ASMEM  ((2*QTILE + 2*KVBUF) * 2)   // bytes = 147456

__global__ __launch_bounds__(256, 1)
void attn_mma()
{
    extern __shared__ __half smh[];
    const uint32_t smb = smem_u32(smh);
    const int tid = threadIdx.x, lane = tid & 31, w = tid >> 5;
    const int g = lane >> 2, tg = lane & 3;
    const int bh = blockIdx.y;
    const int q0 = blockIdx.x * QROWS;
    const size_t hb = (size_t)bh * SEQ * DH;

    const uint32_t Qh_o = 0, Ql_o = QTILE;
    const uint32_t KV_o = 2 * QTILE;

    // ---- prologue: Q (256 rows, h+l) then KV stages 0,1 (128 rows each)
    #pragma unroll
    for (int it = 0; it < 16; ++it) {
        int idx = it * 256 + tid;              // 0..4095
        int tile = idx >> 11;                  // 0: Qh, 1: Ql
        int t2 = idx & 2047;
        int row = t2 >> 3, seg = t2 & 7;
        const __half* src = (tile ? g_ql : g_qh) + hb + (size_t)(q0 + row) * DH + seg * 8;
        CPA16(smb + (tile ? Ql_o : Qh_o) * 2 + (row * 72 + seg * 8) * 2, src);
    }
    const __half* kvsrc[2] = {g_kh, g_vh};
    auto issue_kv = [&](int kt2, int b) {
        #pragma unroll
        for (int it = 0; it < 8; ++it) {
            int idx = it * 256 + tid;          // 0..2047
            int tile = idx >> 10;              // 0: Kh, 1: Vh
            int t2 = idx & 1023;
            int row = t2 >> 3, seg = t2 & 7;   // 128 rows x 8 segs
            const __half* src = kvsrc[tile] + hb + (size_t)(kt2 * 128 + row) * DH + seg * 8;
            uint32_t dst = smb + (KV_o + b * KVBUF + tile * KVTILE + row * 72 + seg * 8) * 2;
            CPA16(dst, src);
        }
    };
    issue_kv(0, 0); CPC();
    issue_kv(1, 1); CPC();

    float o0[8][4], o1[8][4], m0_[2], m1_[2], l0_[2], l1_[2];
    #pragma unroll
    for (int j = 0; j < 8; j++)
        #pragma unroll
        for (int r = 0; r < 4; r++) { o0[j][r] = 0.f; o1[j][r] = 0.f; }
    m0_[0] = m0_[1] = m1_[0] = m1_[1] = __int_as_float(0xff800000);
    l0_[0] = l0_[1] = l1_[0] = l1_[1] = 0.f;

    const int NT2 = SEQ / 128;
    for (int kt2 = 0; kt2 < NT2; ++kt2) {
        const int b = kt2 & 1;
        const uint32_t kvb = KV_o + b * KVBUF;
        CPW(1);
        __syncthreads();

        #pragma unroll
        for (int half = 0; half < 2; ++half) {
            const uint32_t kb = kvb + half * KVHALF;            // K sub-tile
            const uint32_t vb = kvb + KVTILE + half * KVHALF;   // V sub-tile

            // ---- S = Q K^T for both row blocks ----
            float s0[8][4], s1[8][4];
            #pragma unroll
            for (int j = 0; j < 8; j++)
                #pragma unroll
                for (int r = 0; r < 4; r++) { s0[j][r] = 0.f; s1[j][r] = 0.f; }

            #pragma unroll
            for (int ds = 0; ds < 4; ++ds) {
                uint32_t qh0[4], ql0[4], qh1[4], ql1[4];
                {
                    int col = ds * 16 + ((lane >> 4) << 3);
                    int r0 = w * 16 + (lane & 15);
                    int r1 = 128 + w * 16 + (lane & 15);
                    uint32_t a0 = smb + (r0 * 72 + col) * 2;
                    uint32_t a1 = smb + (r1 * 72 + col) * 2;
                    LDSM4(qh0[0], qh0[1], qh0[2], qh0[3], a0 + Qh_o * 2);
                    LDSM4(ql0[0], ql0[1], ql0[2], ql0[3], a0 + Ql_o * 2);
                    LDSM4(qh1[0], qh1[1], qh1[2], qh1[3], a1 + Qh_o * 2);
                    LDSM4(ql1[0], ql1[1], ql1[2], ql1[3], a1 + Ql_o * 2);
                }
                int bcol = ds * 16 + (((lane >> 3) & 1) << 3);
                #pragma unroll
                for (int j = 0; j < 8; ++j) {
                    int r = j * 8 + (lane & 7);
                    uint32_t kd = smb + (kb + r * 72 + bcol) * 2;
                    uint32_t kh2[2];
                    LDSM2(kh2[0], kh2[1], kd);
                    MMA(s0[j], qh0, kh2);
                    MMA(s1[j], qh1, kh2);
                    MMA(s0[j], ql0, kh2);
                    MMA(s1[j], ql1, kh2);
                }
            }

            // ---- online softmax for both row blocks ----
            #pragma unroll
            for (int rb = 0; rb < 2; ++rb) {
                float (*s)[4] = rb ? s1 : s0;
                float (*o)[4] = rb ? o1 : o0;
                float* m_ = rb ? m1_ : m0_;
                float* l_ = rb ? l1_ : l0_;
                #pragma unroll
                for (int rr = 0; rr < 2; ++rr) {
                    float mx = m_[rr];
                    #pragma unroll
                    for (int j = 0; j < 8; ++j) {
                        float v0 = s[j][rr*2+0] * 0.125f, v1 = s[j][rr*2+1] * 0.125f;
                        s[j][rr*2+0] = v0; s[j][rr*2+1] = v1;
                        mx = fmaxf(mx, fmaxf(v0, v1));
                    }
                    mx = fmaxf(mx, __shfl_xor_sync(0xffffffffu, mx, 1));
                    mx = fmaxf(mx, __shfl_xor_sync(0xffffffffu, mx, 2));
                    float alpha = __expf(m_[rr] - mx);
                    m_[rr] = mx;
                    float rs = 0.f;
                    #pragma unroll
                    for (int j = 0; j < 8; ++j) {
                        float e0 = __expf(s[j][rr*2+0] - mx);
                        float e1 = __expf(s[j][rr*2+1] - mx);
                        s[j][rr*2+0] = e0; s[j][rr*2+1] = e1;
                        rs += e0 + e1;
                    }
                    rs += __shfl_xor_sync(0xffffffffu, rs, 1);
                    rs += __shfl_xor_sync(0xffffffffu, rs, 2);
                    l_[rr] = l_[rr] * alpha + rs;
                    #pragma unroll
                    for (int j = 0; j < 8; ++j) {
                        o[j][rr*2+0] *= alpha;
                        o[j][rr*2+1] *= alpha;
                    }
                }
            }

            // ---- O += P V (P split in registers, Vh from smem) ----
            #pragma unroll
            for (int ks = 0; ks < 4; ++ks) {
                uint32_t pa0h[4], pa0l[4], pa1h[4], pa1l[4];
                #pragma unroll
                for (int hi = 0; hi < 2; ++hi) {
                    float* f0 = s0[ks * 2 + hi];
                    float* f1 = s1[ks * 2 + hi];
                    #pragma unroll
                    for (int q = 0; q < 2; ++q) {
                        float u0 = f0[q*2+0], u1 = f0[q*2+1];
                        float w0 = f1[q*2+0], w1 = f1[q*2+1];
                        __half t0 = __float2half_rn(u0), t1 = __float2half_rn(u1);
                        __half r0 = __float2half_rn(w0), r1 = __float2half_rn(w1);
                        pa0h[hi*2+q] = packh2(u0, u1);
                        pa0l[hi*2+q] = packh2(u0 - __half2float(t0), u1 - __half2float(t1));
                        pa1h[hi*2+q] = packh2(w0, w1);
                        pa1l[hi*2+q] = packh2(w0 - __half2float(r0), w1 - __half2float(r1));
                    }
                }
                int vrow = ks * 16 + (lane & 15);
                #pragma unroll
                for (int jn = 0; jn < 8; ++jn) {
                    uint32_t vd = smb + (vb + vrow * 72 + jn * 8) * 2;
                    uint32_t vh2[2];
                    LDSM2T(vh2[0], vh2[1], vd);
                    MMA(o0[jn], pa0h, vh2);
                    MMA(o1[jn], pa1h, vh2);
                    MMA(o0[jn], pa0l, vh2);
                    MMA(o1[jn], pa1l, vh2);
                }
            }
        }

        __syncthreads();
        if (kt2 + 2 < NT2) { issue_kv(kt2 + 2, b); CPC(); }
    }

    // ---- epilogue: normalize, split fp16, store to g_ah/g_al (both rbs) ----
    const int bb = bh >> 4, hh = bh & 15;
    #pragma unroll
    for (int rb = 0; rb < 2; ++rb) {
        float (*o)[4] = rb ? o1 : o0;
        float* l_ = rb ? l1_ : l0_;
        #pragma unroll
        for (int rr = 0; rr < 2; ++rr) {
            float inv = 1.0f / l_[rr];
            int sq = q0 + rb * 128 + w * 16 + g + rr * 8;
            size_t rowo = ((size_t)(bb * SEQ + sq)) * EMBD + hh * DH;
            #pragma unroll
            for (int jn = 0; jn < 8; ++jn) {
                int dd = jn * 8 + tg * 2;
                float v0 = o[jn][rr*2+0] * inv;
                float v1 = o[jn][rr*2+1] * inv;
                __half h0 = __float2half_rn(v0), h1 = __float2half_rn(v1);
                *(__half2*)&g_ah[rowo + dd] = __halves2half2(h0, h1);
                *(__half2*)&g_al[rowo + dd] = __halves2half2(
                    __float2half_rn(v0 - __half2float(h0)),
                    __float2half_rn(v1 - __half2float(h1)));
            }
        }
    }
}

// ============================================================================
extern "C" void kernel_launch(void* const* d_in, const int* in_sizes, int n_in,
                              void* d_out, int out_size)
{
    const float* x     = (const float*)d_in[0];
    const float* W_in  = (const float*)d_in[1];
    const float* b_in  = (const float*)d_in[2];
    const float* W_out = (const float*)d_in[3];
    const float* b_out = (const float*)d_in[4];
    float* out = (float*)d_out;

    cudaFuncSetAttribute(gemm_tc, cudaFuncAttributeMaxDynamicSharedMemorySize, GSMEM);
    cudaFuncSetAttribute(attn_mma, cudaFuncAttributeMaxDynamicSharedMemorySize, ASMEM);

    __half *xh, *xl, *wih, *woh, *ah, *al;
    cudaGetSymbolAddress((void**)&xh,  g_xh);
    cudaGetSymbolAddress((void**)&xl,  g_xl);
    cudaGetSymbolAddress((void**)&wih, g_wih);
    cudaGetSymbolAddress((void**)&woh, g_woh);
    cudaGetSymbolAddress((void**)&ah,  g_ah);
    cudaGetSymbolAddress((void**)&al,  g_al);

    // fp32 -> fp16 splits: x full (hi+lo), weights hi-only
    cvt_kernel<<<(MROWS*KDIM/4)/256, 256>>>(x, xh, xl, MROWS*KDIM/4);
    cvt_hi_kernel<<<(3*EMBD*KDIM/4)/256, 256>>>(W_in, wih, 3*EMBD*KDIM/4);
    cvt_hi_kernel<<<(EMBD*KDIM/4)/256, 256>>>(W_out, woh, EMBD*KDIM/4);

    // QKV: [4096,3072] = X @ W_in^T + b_in -> scatter q(h,l)/k(h)/v(h)
    gemm_tc<<<dim3(3072/128, MROWS/128), 512, GSMEM>>>(xh, xl, wih, b_in, nullptr, 0);

    // flash attention (HMMA, 2-term split, 128-row KV stages)
    attn_mma<<<dim3(SEQ/QROWS, BATCH*NH), 256, ASMEM>>>();

    // out-proj: [4096,1024] = Attn @ W_out^T + b_out
    gemm_tc<<<dim3(EMBD/128, MROWS/128), 512, GSMEM>>>(ah, al, woh, b_out, out, 1);
}

// round 12
// speedup vs baseline: 5.1654x; 1.3133x over previous
#include <cuda_runtime.h>
#include <cuda_fp16.h>
#include <cstdint>

#define EMBD  1024
#define NH    16
#define DH    64
#define BATCH 2
#define SEQ   2048
#define MROWS 4096
#define KDIM  1024

// ---------------- scratch (device globals: allocation-free) ----------------
__device__ __align__(16) __half g_xh[MROWS*KDIM];
__device__ __align__(16) __half g_xl[MROWS*KDIM];
__device__ __align__(16) __half g_wih[3*EMBD*KDIM];
__device__ __align__(16) __half g_woh[EMBD*KDIM];
__device__ __align__(16) __half g_qh[BATCH*NH*SEQ*DH];
__device__ __align__(16) __half g_kh[BATCH*NH*SEQ*DH];
__device__ __align__(16) __half g_vh[BATCH*NH*SEQ*DH];
__device__ __align__(16) __half g_ah[MROWS*EMBD];
__device__ __align__(16) __half g_al[MROWS*EMBD];

// ---------------- PTX helpers (sm_80-level: valid under compute_103) -------
__device__ __forceinline__ uint32_t smem_u32(const void* p) {
    uint32_t a;
    asm("{ .reg .u64 t; cvta.to.shared.u64 t, %1; cvt.u32.u64 %0, t; }" : "=r"(a) : "l"(p));
    return a;
}
#define CPA16(dst, src) asm volatile("cp.async.cg.shared.global [%0], [%1], 16;" :: "r"(dst), "l"(src))
#define CPC()   asm volatile("cp.async.commit_group;" ::: "memory")
#define CPW(n)  asm volatile("cp.async.wait_group %0;" :: "n"(n) : "memory")

#define LDSM4(r0,r1,r2,r3,a) \
    asm volatile("ldmatrix.sync.aligned.m8n8.x4.shared.b16 {%0,%1,%2,%3}, [%4];" \
        : "=r"(r0),"=r"(r1),"=r"(r2),"=r"(r3) : "r"(a))
#define LDSM2(r0,r1,a) \
    asm volatile("ldmatrix.sync.aligned.m8n8.x2.shared.b16 {%0,%1}, [%2];" \
        : "=r"(r0),"=r"(r1) : "r"(a))
#define LDSM2T(r0,r1,a) \
    asm volatile("ldmatrix.sync.aligned.m8n8.x2.trans.shared.b16 {%0,%1}, [%2];" \
        : "=r"(r0),"=r"(r1) : "r"(a))

#define MMA(d, a, b) \
    asm volatile("mma.sync.aligned.m16n8k16.row.col.f32.f16.f16.f32 " \
        "{%0,%1,%2,%3},{%4,%5,%6,%7},{%8,%9},{%0,%1,%2,%3};" \
        : "+f"((d)[0]),"+f"((d)[1]),"+f"((d)[2]),"+f"((d)[3]) \
        : "r"((a)[0]),"r"((a)[1]),"r"((a)[2]),"r"((a)[3]),"r"((b)[0]),"r"((b)[1]))

__device__ __forceinline__ uint32_t packh2(float a, float b) {
    __half2 h = __halves2half2(__float2half_rn(a), __float2half_rn(b));
    return *reinterpret_cast<uint32_t*>(&h);
}

// ---------------- fp32 -> fp16 hi/lo split ----------------
__global__ __launch_bounds__(256)
void cvt_kernel(const float* __restrict__ s, __half* __restrict__ hi,
                __half* __restrict__ lo, int n4)
{
    int i = blockIdx.x * 256 + threadIdx.x;
    if (i >= n4) return;
    float4 v = ((const float4*)s)[i];
    __half h0 = __float2half_rn(v.x), h1 = __float2half_rn(v.y);
    __half h2 = __float2half_rn(v.z), h3 = __float2half_rn(v.w);
    ((__half2*)hi)[2*i]   = __halves2half2(h0, h1);
    ((__half2*)hi)[2*i+1] = __halves2half2(h2, h3);
    ((__half2*)lo)[2*i]   = __halves2half2(
        __float2half_rn(v.x - __half2float(h0)), __float2half_rn(v.y - __half2float(h1)));
    ((__half2*)lo)[2*i+1] = __halves2half2(
        __float2half_rn(v.z - __half2float(h2)), __float2half_rn(v.w - __half2float(h3)));
}

__global__ __launch_bounds__(256)
void cvt_hi_kernel(const float* __restrict__ s, __half* __restrict__ hi, int n4)
{
    int i = blockIdx.x * 256 + threadIdx.x;
    if (i >= n4) return;
    float4 v = ((const float4*)s)[i];
    ((__half2*)hi)[2*i]   = __halves2half2(__float2half_rn(v.x), __float2half_rn(v.y));
    ((__half2*)hi)[2*i+1] = __halves2half2(__float2half_rn(v.z), __float2half_rn(v.w));
}

// ============================================================================
// HMMA NT GEMM: C = (Ah[+Al])[M,K] * Bh[N,K]^T, K=1024.
// mode 0 (QKV): Q band (sel==0) uses 2-term A split; K/V bands 1-term
//               (their noise enters only softmax-averaged paths).
// mode 1 (out-proj): always 2-term.
// BK=64, 3-stage cp.async pipeline. 16 warps (4x4), warp tile 32x32.
// Rows 64 halves data + 8 pad = 144B (conflict-free ldmatrix).
// ============================================================================
#define GROW   144              // bytes per smem row
#define GTILE  (128*GROW)       // 18432 B per tile
#define GSTG   (3*GTILE)        // 55296 B per stage (Ah, Al, Bh)
#define GSMEM  (3*GSTG)         // 165888 B

__global__ __launch_bounds__(512, 1)
void gemm_tc(const __half* __restrict__ Ah, const __half* __restrict__ Al,
             const __half* __restrict__ Bh,
             const float* __restrict__ bias, float* __restrict__ outp, int mode)
{
    extern __shared__ char smg[];
    const uint32_t smb = smem_u32(smg);
    const int tid = threadIdx.x, lane = tid & 31, wid = tid >> 5;
    const int wm = wid >> 2, wn = wid & 3;          // 4 x 4 warp grid
    const int m0 = blockIdx.y * 128, n0 = blockIdx.x * 128;
    const int sel = n0 >> 10;                        // QKV band: 0=q 1=k 2=v
    const bool use_al = (mode != 0) || (sel == 0);   // 2-term only where needed

    const __half* srcs[3] = {Ah, Al, Bh};

    auto issue_stage = [&](int kt, int st) {
        #pragma unroll
        for (int it = 0; it < 6; ++it) {
            int idx = it * 512 + tid;           // 0..3071
            int tile = idx >> 10;               // 0..2
            if (tile == 1 && !use_al) continue;
            int t2 = idx & 1023;
            int row = t2 >> 3, seg = t2 & 7;    // 128 rows x 8 16B-segs
            int grow = (tile < 2 ? m0 : n0) + row;
            const __half* src = srcs[tile] + (size_t)grow * KDIM + kt * 64 + seg * 8;
            uint32_t dst = smb + st * GSTG + tile * GTILE + row * GROW + seg * 16;
            CPA16(dst, src);
        }
    };

    float acc[2][4][4];
    #pragma unroll
    for (int i = 0; i < 2; i++)
        #pragma unroll
        for (int j = 0; j < 4; j++)
            #pragma unroll
            for (int r = 0; r < 4; r++) acc[i][j][r] = 0.f;

    issue_stage(0, 0); CPC();
    issue_stage(1, 1); CPC();

    const int NK = KDIM / 64;
    for (int kt = 0; kt < NK; ++kt) {
        CPW(1);
        __syncthreads();
        if (kt + 2 < NK) { issue_stage(kt + 2, (kt + 2) % 3); CPC(); }

        const uint32_t base = smb + (kt % 3) * GSTG;
        #pragma unroll
        for (int ks = 0; ks < 4; ++ks) {
            uint32_t a_h[2][4], a_l[2][4];
            const int acol = ks * 16 + ((lane >> 4) << 3);
            #pragma unroll
            for (int i = 0; i < 2; ++i) {
                int r = wm * 32 + i * 16 + (lane & 15);
                uint32_t ad = base + r * GROW + acol * 2;
                LDSM4(a_h[i][0], a_h[i][1], a_h[i][2], a_h[i][3], ad);
                if (use_al)
                    LDSM4(a_l[i][0], a_l[i][1], a_l[i][2], a_l[i][3], ad + GTILE);
            }
            const int bcol = ks * 16 + (((lane >> 3) & 1) << 3);
            #pragma unroll
            for (int j = 0; j < 4; ++j) {
                int r = wn * 32 + j * 8 + (lane & 7);
                uint32_t bd = base + 2 * GTILE + r * GROW + bcol * 2;
                uint32_t b_h[2];
                LDSM2(b_h[0], b_h[1], bd);
                #pragma unroll
                for (int i = 0; i < 2; ++i) {
                    MMA(acc[i][j], a_h[i], b_h);
                    if (use_al) MMA(acc[i][j], a_l[i], b_h);
                }
            }
        }
    }

    // ---------------- epilogue ----------------
    const int g = lane >> 2, tg = lane & 3;
    if (mode == 0) {
        __half* dh = (sel == 0) ? g_qh : (sel == 1) ? g_kh : g_vh;
        #pragma unroll
        for (int i = 0; i < 2; ++i) {
            #pragma unroll
            for (int j = 0; j < 4; ++j) {
                int n = n0 + wn * 32 + j * 8 + tg * 2;
                int hh = (n & 1023) >> 6, dd = n & 63;
                float b0 = __ldg(bias + n), b1 = __ldg(bias + n + 1);
                #pragma unroll
                for (int rr = 0; rr < 2; ++rr) {
                    int m = m0 + wm * 32 + i * 16 + g + rr * 8;
                    int bb = m >> 11, ss = m & 2047;
                    float v0 = acc[i][j][rr*2+0] + b0;
                    float v1 = acc[i][j][rr*2+1] + b1;
                    size_t o = (((size_t)(bb * NH + hh)) * SEQ + ss) * DH + dd;
                    *(__half2*)&dh[o] = __halves2half2(__float2half_rn(v0),
                                                       __float2half_rn(v1));
                }
            }
        }
    } else {
        #pragma unroll
        for (int i = 0; i < 2; ++i) {
            #pragma unroll
            for (int j = 0; j < 4; ++j) {
                int n = n0 + wn * 32 + j * 8 + tg * 2;
                float b0 = __ldg(bias + n), b1 = __ldg(bias + n + 1);
                #pragma unroll
                for (int rr = 0; rr < 2; ++rr) {
                    int m = m0 + wm * 32 + i * 16 + g + rr * 8;
                    float2 w;
                    w.x = acc[i][j][rr*2+0] + b0;
                    w.y = acc[i][j][rr*2+1] + b1;
                    *(float2*)&outp[(size_t)m * EMBD + n] = w;
                }
            }
        }
    }
}

// ============================================================================
// Flash attention, HMMA single-term (softmax-averaged noise paths).
// CTA = 256 q-rows of one (b,h); 8 warps x two 16-row blocks.
// KV staged 128 rows per cp.async stage (2 x 64-row passes per barrier pair).
// S = Qh Kh^T ; O += Ph Vh.  Output kept 2-term (hi+lo) for out-proj.
// smem half-stride 72 (144B rows): conflict-free ldmatrix (incl. trans).
// ============================================================================
#define QROWS  256
#define QTILE  (QROWS*72)      // halves for Qh
#define KVHALF 4608            // 64*72 halves (one 64-row sub-tile)
#define KVTILE (2*KVHALF)      // 128*72 halves per K or V tile
#define KVBUF  (2*KVTILE)      // Kh, Vh
#define ASMEM  ((QTILE + 2*KVBUF) * 2)   // bytes = 110592

__global__ __launch_bounds__(256, 1)
void attn_mma()
{
    extern __shared__ __half smh[];
    const uint32_t smb = smem_u32(smh);
    const int tid = threadIdx.x, lane = tid & 31, w = tid >> 5;
    const int g = lane >> 2, tg = lane & 3;
    const int bh = blockIdx.y;
    const int q0 = blockIdx.x * QROWS;
    const size_t hb = (size_t)bh * SEQ * DH;

    const uint32_t KV_o = QTILE;

    // ---- prologue: Qh (256 rows) then KV stages 0,1 (128 rows each)
    #pragma unroll
    for (int it = 0; it < 8; ++it) {
        int idx = it * 256 + tid;              // 0..2047
        int row = idx >> 3, seg = idx & 7;
        const __half* src = g_qh + hb + (size_t)(q0 + row) * DH + seg * 8;
        CPA16(smb + (row * 72 + seg * 8) * 2, src);
    }
    const __half* kvsrc[2] = {g_kh, g_vh};
    auto issue_kv = [&](int kt2, int b) {
        #pragma unroll
        for (int it = 0; it < 8; ++it) {
            int idx = it * 256 + tid;          // 0..2047
            int tile = idx >> 10;              // 0: Kh, 1: Vh
            int t2 = idx & 1023;
            int row = t2 >> 3, seg = t2 & 7;   // 128 rows x 8 segs
            const __half* src = kvsrc[tile] + hb + (size_t)(kt2 * 128 + row) * DH + seg * 8;
            uint32_t dst = smb + (KV_o + b * KVBUF + tile * KVTILE + row * 72 + seg * 8) * 2;
            CPA16(dst, src);
        }
    };
    issue_kv(0, 0); CPC();
    issue_kv(1, 1); CPC();

    float o0[8][4], o1[8][4], m0_[2], m1_[2], l0_[2], l1_[2];
    #pragma unroll
    for (int j = 0; j < 8; j++)
        #pragma unroll
        for (int r = 0; r < 4; r++) { o0[j][r] = 0.f; o1[j][r] = 0.f; }
    m0_[0] = m0_[1] = m1_[0] = m1_[1] = __int_as_float(0xff800000);
    l0_[0] = l0_[1] = l1_[0] = l1_[1] = 0.f;

    const int NT2 = SEQ / 128;
    for (int kt2 = 0; kt2 < NT2; ++kt2) {
        const int b = kt2 & 1;
        const uint32_t kvb = KV_o + b * KVBUF;
        CPW(1);
        __syncthreads();

        #pragma unroll
        for (int half = 0; half < 2; ++half) {
            const uint32_t kb = kvb + half * KVHALF;            // K sub-tile
            const uint32_t vb = kvb + KVTILE + half * KVHALF;   // V sub-tile

            // ---- S = Qh Kh^T for both row blocks ----
            float s0[8][4], s1[8][4];
            #pragma unroll
            for (int j = 0; j < 8; j++)
                #pragma unroll
                for (int r = 0; r < 4; r++) { s0[j][r] = 0.f; s1[j][r] = 0.f; }

            #pragma unroll
            for (int ds = 0; ds < 4; ++ds) {
                uint32_t qh0[4], qh1[4];
                {
                    int col = ds * 16 + ((lane >> 4) << 3);
                    int r0 = w * 16 + (lane & 15);
                    int r1 = 128 + w * 16 + (lane & 15);
                    LDSM4(qh0[0], qh0[1], qh0[2], qh0[3], smb + (r0 * 72 + col) * 2);
                    LDSM4(qh1[0], qh1[1], qh1[2], qh1[3], smb + (r1 * 72 + col) * 2);
                }
                int bcol = ds * 16 + (((lane >> 3) & 1) << 3);
                #pragma unroll
                for (int j = 0; j < 8; ++j) {
                    int r = j * 8 + (lane & 7);
                    uint32_t kd = smb + (kb + r * 72 + bcol) * 2;
                    uint32_t kh2[2];
                    LDSM2(kh2[0], kh2[1], kd);
                    MMA(s0[j], qh0, kh2);
                    MMA(s1[j], qh1, kh2);
                }
            }

            // ---- online softmax for both row blocks ----
            #pragma unroll
            for (int rb = 0; rb < 2; ++rb) {
                float (*s)[4] = rb ? s1 : s0;
                float (*o)[4] = rb ? o1 : o0;
                float* m_ = rb ? m1_ : m0_;
                float* l_ = rb ? l1_ : l0_;
                #pragma unroll
                for (int rr = 0; rr < 2; ++rr) {
                    float mx = m_[rr];
                    #pragma unroll
                    for (int j = 0; j < 8; ++j) {
                        float v0 = s[j][rr*2+0] * 0.125f, v1 = s[j][rr*2+1] * 0.125f;
                        s[j][rr*2+0] = v0; s[j][rr*2+1] = v1;
                        mx = fmaxf(mx, fmaxf(v0, v1));
                    }
                    mx = fmaxf(mx, __shfl_xor_sync(0xffffffffu, mx, 1));
                    mx = fmaxf(mx, __shfl_xor_sync(0xffffffffu, mx, 2));
                    float alpha = __expf(m_[rr] - mx);
                    m_[rr] = mx;
                    float rs = 0.f;
                    #pragma unroll
                    for (int j = 0; j < 8; ++j) {
                        float e0 = __expf(s[j][rr*2+0] - mx);
                        float e1 = __expf(s[j][rr*2+1] - mx);
                        s[j][rr*2+0] = e0; s[j][rr*2+1] = e1;
                        rs += e0 + e1;
                    }
                    rs += __shfl_xor_sync(0xffffffffu, rs, 1);
                    rs += __shfl_xor_sync(0xffffffffu, rs, 2);
                    l_[rr] = l_[rr] * alpha + rs;
                    #pragma unroll
                    for (int j = 0; j < 8; ++j) {
                        o[j][rr*2+0] *= alpha;
                        o[j][rr*2+1] *= alpha;
                    }
                }
            }

            // ---- O += Ph Vh (P rounded to fp16; noise averaged by softmax) ----
            #pragma unroll
            for (int ks = 0; ks < 4; ++ks) {
                uint32_t pa0h[4], pa1h[4];
                #pragma unroll
                for (int hi = 0; hi < 2; ++hi) {
                    float* f0 = s0[ks * 2 + hi];
                    float* f1 = s1[ks * 2 + hi];
                    #pragma unroll
                    for (int q = 0; q < 2; ++q) {
                        pa0h[hi*2+q] = packh2(f0[q*2+0], f0[q*2+1]);
                        pa1h[hi*2+q] = packh2(f1[q*2+0], f1[q*2+1]);
                    }
                }
                int vrow = ks * 16 + (lane & 15);
                #pragma unroll
                for (int jn = 0; jn < 8; ++jn) {
                    uint32_t vd = smb + (vb + vrow * 72 + jn * 8) * 2;
                    uint32_t vh2[2];
                    LDSM2T(vh2[0], vh2[1], vd);
                    MMA(o0[jn], pa0h, vh2);
                    MMA(o1[jn], pa1h, vh2);
                }
            }
        }

        __syncthreads();
        if (kt2 + 2 < NT2) { issue_kv(kt2 + 2, b); CPC(); }
    }

    // ---- epilogue: normalize, split fp16 (hi+lo kept for out-proj) ----
    const int bb = bh >> 4, hh = bh & 15;
    #pragma unroll
    for (int rb = 0; rb < 2; ++rb) {
        float (*o)[4] = rb ? o1 : o0;
        float* l_ = rb ? l1_ : l0_;
        #pragma unroll
        for (int rr = 0; rr < 2; ++rr) {
            float inv = 1.0f / l_[rr];
            int sq = q0 + rb * 128 + w * 16 + g + rr * 8;
            size_t rowo = ((size_t)(bb * SEQ + sq)) * EMBD + hh * DH;
            #pragma unroll
            for (int jn = 0; jn < 8; ++jn) {
                int dd = jn * 8 + tg * 2;
                float v0 = o[jn][rr*2+0] * inv;
                float v1 = o[jn][rr*2+1] * inv;
                __half h0 = __float2half_rn(v0), h1 = __float2half_rn(v1);
                *(__half2*)&g_ah[rowo + dd] = __halves2half2(h0, h1);
                *(__half2*)&g_al[rowo + dd] = __halves2half2(
                    __float2half_rn(v0 - __half2float(h0)),
                    __float2half_rn(v1 - __half2float(h1)));
            }
        }
    }
}

// ============================================================================
extern "C" void kernel_launch(void* const* d_in, const int* in_sizes, int n_in,
                              void* d_out, int out_size)
{
    const float* x     = (const float*)d_in[0];
    const float* W_in  = (const float*)d_in[1];
    const float* b_in  = (const float*)d_in[2];
    const float* W_out = (const float*)d_in[3];
    const float* b_out = (const float*)d_in[4];
    float* out = (float*)d_out;

    cudaFuncSetAttribute(gemm_tc, cudaFuncAttributeMaxDynamicSharedMemorySize, GSMEM);
    cudaFuncSetAttribute(attn_mma, cudaFuncAttributeMaxDynamicSharedMemorySize, ASMEM);

    __half *xh, *xl, *wih, *woh, *ah, *al;
    cudaGetSymbolAddress((void**)&xh,  g_xh);
    cudaGetSymbolAddress((void**)&xl,  g_xl);
    cudaGetSymbolAddress((void**)&wih, g_wih);
    cudaGetSymbolAddress((void**)&woh, g_woh);
    cudaGetSymbolAddress((void**)&ah,  g_ah);
    cudaGetSymbolAddress((void**)&al,  g_al);

    // fp32 -> fp16 splits: x full (hi+lo, Q band needs lo), weights hi-only
    cvt_kernel<<<(MROWS*KDIM/4)/256, 256>>>(x, xh, xl, MROWS*KDIM/4);
    cvt_hi_kernel<<<(3*EMBD*KDIM/4)/256, 256>>>(W_in, wih, 3*EMBD*KDIM/4);
    cvt_hi_kernel<<<(EMBD*KDIM/4)/256, 256>>>(W_out, woh, EMBD*KDIM/4);

    // QKV: Q band 2-term, K/V bands 1-term -> scatter q/k/v (hi-only)
    gemm_tc<<<dim3(3072/128, MROWS/128), 512, GSMEM>>>(xh, xl, wih, b_in, nullptr, 0);

    // flash attention (HMMA, single-term S and PV)
    attn_mma<<<dim3(SEQ/QROWS, BATCH*NH), 256, ASMEM>>>();

    // out-proj: 2-term: [4096,1024] = (Ah+Al) @ W_out^T + b_out
    gemm_tc<<<dim3(EMBD/128, MROWS/128), 512, GSMEM>>>(ah, al, woh, b_out, out, 1);
}